// round 11
// baseline (speedup 1.0000x reference)
#include <cuda_runtime.h>
#include <math.h>
#include <float.h>

#define NB 32
#define NS 32768
#define NF 128
#define DM 128

// ------------------------- scratch (device globals) -------------------------
__device__ float2 g_twid[512];            // exp(-2*pi*i*k/1024)
__device__ float2 g_P[64 * 1024];         // conj(FFT(w_2c - i w_2c+1)), scrambled
__device__ float g_ewT[161 * 128];        // transposed embed weights
__device__ float g_chunk[NB * NF * DM];
__device__ float g_h[NB * NF * DM];
__device__ float g_attno[NB * NF * DM];
__device__ int   g_topidx[NB * 16];
__device__ float g_topval[NB * 16];

// ------------------------- butterflies ---------------------------------------
__device__ __forceinline__ void bf_dif(float& ar, float& ai, float& br, float& bi, float2 w)
{
    float xr = ar - br, xi = ai - bi;
    ar += br; ai += bi;
    br = xr * w.x - xi * w.y;
    bi = xr * w.y + xi * w.x;
}
__device__ __forceinline__ void bf_dit(float& ar, float& ai, float& br, float& bi, float2 w)
{
    float tr = br * w.x + bi * w.y;
    float ti = bi * w.x - br * w.y;
    br = ar - tr; bi = ai - ti;
    ar += tr; ai += ti;
}

// ------------------------- forward 1024-pt DIF (in-place, natural->bitrev) ---
__device__ __forceinline__ void fft1024_dif(float* re, float* im, const float2* tw, int tid)
{
    {   // stages h=512, 256
        int r = tid;
        float ar = re[r],       ai = im[r];
        float br = re[r + 256], bi = im[r + 256];
        float cr = re[r + 512], ci = im[r + 512];
        float dr = re[r + 768], di = im[r + 768];
        bf_dif(ar, ai, cr, ci, tw[r]);
        bf_dif(br, bi, dr, di, tw[r + 256]);
        float2 v = tw[2 * r];
        bf_dif(ar, ai, br, bi, v);
        bf_dif(cr, ci, dr, di, v);
        re[r] = ar;       im[r] = ai;
        re[r + 256] = br; im[r + 256] = bi;
        re[r + 512] = cr; im[r + 512] = ci;
        re[r + 768] = dr; im[r + 768] = di;
    }
    __syncthreads();
    {   // stages h=128, 64
        int q = tid >> 6, r = tid & 63, i0 = q * 256 + r;
        float ar = re[i0],       ai = im[i0];
        float br = re[i0 + 64],  bi = im[i0 + 64];
        float cr = re[i0 + 128], ci = im[i0 + 128];
        float dr = re[i0 + 192], di = im[i0 + 192];
        bf_dif(ar, ai, cr, ci, tw[4 * r]);
        bf_dif(br, bi, dr, di, tw[4 * r + 256]);
        float2 v = tw[8 * r];
        bf_dif(ar, ai, br, bi, v);
        bf_dif(cr, ci, dr, di, v);
        re[i0] = ar;       im[i0] = ai;
        re[i0 + 64] = br;  im[i0 + 64] = bi;
        re[i0 + 128] = cr; im[i0 + 128] = ci;
        re[i0 + 192] = dr; im[i0 + 192] = di;
    }
    __syncthreads();
    {   // stages h=32..4 (shuffle), 2,1 (in-thread)
        float4 R = ((const float4*)re)[tid];
        float4 I = ((const float4*)im)[tid];
        float vr[4] = {R.x, R.y, R.z, R.w};
        float vi[4] = {I.x, I.y, I.z, I.w};
#pragma unroll
        for (int s = 3; s >= 0; s--) {
            const int mask = 1 << s;
            const int step = 128 >> s;
            const int kb = 4 * (tid & (mask - 1));
            const bool up = (tid & mask) != 0;
#pragma unroll
            for (int j = 0; j < 4; j++) {
                float orr = __shfl_xor_sync(0xffffffffu, vr[j], mask);
                float oii = __shfl_xor_sync(0xffffffffu, vi[j], mask);
                float2 w = tw[(kb + j) * step];
                float sr = vr[j] + orr, si = vi[j] + oii;
                float dr = orr - vr[j], di = oii - vi[j];
                float pr = dr * w.x - di * w.y;
                float pi = dr * w.y + di * w.x;
                vr[j] = up ? pr : sr;
                vi[j] = up ? pi : si;
            }
        }
        {
            float s0r = vr[0] + vr[2], s0i = vi[0] + vi[2];
            float d0r = vr[0] - vr[2], d0i = vi[0] - vi[2];
            vr[0] = s0r; vi[0] = s0i; vr[2] = d0r; vi[2] = d0i;
            float s1r = vr[1] + vr[3], s1i = vi[1] + vi[3];
            float d1r = vr[1] - vr[3], d1i = vi[1] - vi[3];
            vr[1] = s1r; vi[1] = s1i;
            vr[3] = d1i; vi[3] = -d1r;
        }
        {
            float t0r = vr[0] + vr[1], t0i = vi[0] + vi[1];
            float t1r = vr[0] - vr[1], t1i = vi[0] - vi[1];
            float t2r = vr[2] + vr[3], t2i = vi[2] + vi[3];
            float t3r = vr[2] - vr[3], t3i = vi[2] - vi[3];
            vr[0] = t0r; vi[0] = t0i; vr[1] = t1r; vi[1] = t1i;
            vr[2] = t2r; vi[2] = t2i; vr[3] = t3r; vi[3] = t3i;
        }
        ((float4*)re)[tid] = make_float4(vr[0], vr[1], vr[2], vr[3]);
        ((float4*)im)[tid] = make_float4(vi[0], vi[1], vi[2], vi[3]);
    }
    __syncthreads();
}

// ------------------------- precompute kernels --------------------------------
__global__ void twid_kernel()
{
    int k = blockIdx.x * 256 + threadIdx.x;
    if (k < 512) {
        double a = -2.0 * 3.14159265358979323846 * (double)k / 1024.0;
        g_twid[k] = make_float2((float)cos(a), (float)sin(a));
    }
}

__global__ __launch_bounds__(256) void filt_kernel(const float* __restrict__ fb)
{
    __shared__ __align__(16) float re[1024], im[1024];
    __shared__ __align__(16) float2 tw[512];
    const int c = blockIdx.x, tid = threadIdx.x;
    tw[tid] = g_twid[tid]; tw[tid + 256] = g_twid[tid + 256];
    for (int i = tid; i < 1024; i += 256) {
        re[i] = (i < 512) ? fb[(size_t)(2 * c) * 512 + i] : 0.f;
        im[i] = (i < 512) ? -fb[(size_t)(2 * c + 1) * 512 + i] : 0.f;
    }
    __syncthreads();
    fft1024_dif(re, im, tw, tid);
    for (int i = tid; i < 1024; i += 256)
        g_P[(size_t)c * 1024 + i] = make_float2(re[i], -im[i]);
}

__global__ void ewt_kernel(const float* __restrict__ ew)
{
    int i = blockIdx.x * 256 + threadIdx.x;
    if (i < 161 * 128) {
        int j = i >> 7, c = i & 127;
        g_ewT[j * 128 + c] = ew[(size_t)c * 161 + j];
    }
}

// ---- trip A: fused pointwise(U*P) + DIT stages 1..64 (sign-folded twiddles) --
__device__ __forceinline__ void ifft_stageA(const float ur[4], const float ui[4],
                                            const float4* __restrict__ Pp,
                                            const float2 w2[20], int tid,
                                            float2* zc)
{
    float4 P0 = Pp[2 * tid], P1 = Pp[2 * tid + 1];
    float vr[4], vi[4];
    vr[0] = ur[0] * P0.x - ui[0] * P0.y; vi[0] = ur[0] * P0.y + ui[0] * P0.x;
    vr[1] = ur[1] * P0.z - ui[1] * P0.w; vi[1] = ur[1] * P0.w + ui[1] * P0.z;
    vr[2] = ur[2] * P1.x - ui[2] * P1.y; vi[2] = ur[2] * P1.y + ui[2] * P1.x;
    vr[3] = ur[3] * P1.z - ui[3] * P1.w; vi[3] = ur[3] * P1.w + ui[3] * P1.z;
    {   // h=1 (Wc=1)
        float t0r = vr[0] + vr[1], t0i = vi[0] + vi[1];
        float t1r = vr[0] - vr[1], t1i = vi[0] - vi[1];
        float t2r = vr[2] + vr[3], t2i = vi[2] + vi[3];
        float t3r = vr[2] - vr[3], t3i = vi[2] - vi[3];
        vr[0] = t0r; vi[0] = t0i; vr[1] = t1r; vi[1] = t1i;
        vr[2] = t2r; vi[2] = t2i; vr[3] = t3r; vi[3] = t3i;
    }
    {   // h=2: (0,2) Wc=1; (1,3) Wc=(0,1)
        float s0r = vr[0] + vr[2], s0i = vi[0] + vi[2];
        float d0r = vr[0] - vr[2], d0i = vi[0] - vi[2];
        vr[0] = s0r; vi[0] = s0i; vr[2] = d0r; vi[2] = d0i;
        float tr = -vi[3], ti = vr[3];
        float nr = vr[1] + tr, ni = vi[1] + ti;
        float mr = vr[1] - tr, mi = vi[1] - ti;
        vr[1] = nr; vi[1] = ni; vr[3] = mr; vi[3] = mi;
    }
#pragma unroll
    for (int s = 0; s < 5; s++) {               // h = 4,8,16,32,64
        const int mask = 1 << s;
        const bool up = (tid & mask) != 0;
#pragma unroll
        for (int j = 0; j < 4; j++) {
            float orr = __shfl_xor_sync(0xffffffffu, vr[j], mask);
            float oii = __shfl_xor_sync(0xffffffffu, vi[j], mask);
            float Xr = up ? orr : vr[j];
            float Xi = up ? oii : vi[j];
            float Yr = up ? vr[j] : orr;
            float Yi = up ? vi[j] : oii;
            float2 W = w2[s * 4 + j];
            vr[j] = fmaf(W.x, Yr, fmaf(-W.y, Yi, Xr));
            vi[j] = fmaf(W.x, Yi, fmaf(W.y, Yr, Xi));
        }
    }
    ((float4*)zc)[2 * tid]     = make_float4(vr[0], vi[0], vr[1], vi[1]);
    ((float4*)zc)[2 * tid + 1] = make_float4(vr[2], vi[2], vr[3], vi[3]);
}

// ------------------------- FFT conv + |.| + pool -----------------------------
__global__ __launch_bounds__(256) void conv_fft_kernel(const float* __restrict__ x)
{
    __shared__ __align__(16) float uRe[1024], uIm[1024];
    __shared__ __align__(16) float2 zc[2048];
    __shared__ __align__(16) float2 tw[512];
    __shared__ float cs0[128], cs1[128];
    __shared__ float wpart[2][4][4];
    const int seg = blockIdx.x, b = blockIdx.y;
    const int tid = threadIdx.x, w = tid >> 5, lane = tid & 31;

    tw[tid] = g_twid[tid]; tw[tid + 256] = g_twid[tid + 256];
    const float* xb = x + (size_t)b * NS;
    const int base = seg * 512 - 256;
    for (int i = tid; i < 1024; i += 256) {
        int g = base + i;
        uRe[i] = (g >= 0 && g < NS) ? xb[g] : 0.f;
        uIm[i] = 0.f;
    }
    if (tid < 128) { cs0[tid] = 0.f; cs1[tid] = 0.f; }
    __syncthreads();
    fft1024_dif(uRe, uIm, tw, tid);

    // hoist loop invariants
    float ur[4], ui[4];
    {
        float4 R = ((const float4*)uRe)[tid];
        float4 I = ((const float4*)uIm)[tid];
        ur[0] = R.x; ur[1] = R.y; ur[2] = R.z; ur[3] = R.w;
        ui[0] = I.x; ui[1] = I.y; ui[2] = I.z; ui[3] = I.w;
    }
    // sign-folded stage-A twiddles: w2 = (up ? -1 : +1) * conj(tw)
    float2 w2[20];
#pragma unroll
    for (int s = 0; s < 5; s++) {
        const int mask = 1 << s;
        const bool up = (tid & mask) != 0;
        const int ib = tid & (mask - 1);
#pragma unroll
        for (int j = 0; j < 4; j++) {
            float2 t = tw[(4 * ib + j) * (128 >> s)];
            w2[s * 4 + j] = up ? make_float2(-t.x, t.y) : make_float2(t.x, -t.y);
        }
    }
    const int rB = tid & 127;
    const float2 t4r  = tw[4 * rB];
    const float2 t2r  = tw[2 * rB];
    const float2 t2r2 = tw[2 * rB + 256];
    const float2 t5a = tw[rB], t5b = tw[rB + 128], t5c = tw[rB + 256], t5d = tw[rB + 384];

    for (int p = 0; p < 64; p += 2) {
        ifft_stageA(ur, ui, (const float4*)(g_P + (size_t)p * 1024), w2, tid, zc);
        ifft_stageA(ur, ui, (const float4*)(g_P + (size_t)(p + 1) * 1024), w2, tid,
                    zc + 1024);
        __syncthreads();

        // phase BC in registers
        const int sP = tid >> 7;
        const float2* zs = zc + (sP << 10);
        float xr[8], xi[8];
#pragma unroll
        for (int k = 0; k < 8; k++) {
            float2 t = zs[rB + (k << 7)];
            xr[k] = t.x; xi[k] = t.y;
        }
        bf_dit(xr[0], xi[0], xr[1], xi[1], t4r);
        bf_dit(xr[2], xi[2], xr[3], xi[3], t4r);
        bf_dit(xr[4], xi[4], xr[5], xi[5], t4r);
        bf_dit(xr[6], xi[6], xr[7], xi[7], t4r);
        bf_dit(xr[0], xi[0], xr[2], xi[2], t2r);
        bf_dit(xr[1], xi[1], xr[3], xi[3], t2r2);
        bf_dit(xr[4], xi[4], xr[6], xi[6], t2r);
        bf_dit(xr[5], xi[5], xr[7], xi[7], t2r2);
        {
            float tr, ti;
            tr = xr[4] * t5a.x + xi[4] * t5a.y; ti = xi[4] * t5a.x - xr[4] * t5a.y;
            xr[0] += tr; xi[0] += ti;
            tr = xr[5] * t5b.x + xi[5] * t5b.y; ti = xi[5] * t5b.x - xr[5] * t5b.y;
            xr[1] += tr; xi[1] += ti;
            tr = xr[6] * t5c.x + xi[6] * t5c.y; ti = xi[6] * t5c.x - xr[6] * t5c.y;
            xr[2] += tr; xi[2] += ti;
            tr = xr[7] * t5d.x + xi[7] * t5d.y; ti = xi[7] * t5d.x - xr[7] * t5d.y;
            xr[3] += tr; xi[3] += ti;
        }
        float v0 = fabsf(xr[0]) + fabsf(xr[1]);
        float v1 = fabsf(xi[0]) + fabsf(xi[1]);
        float v2 = fabsf(xr[2]) + fabsf(xr[3]);
        float v3 = fabsf(xi[2]) + fabsf(xi[3]);
#pragma unroll
        for (int o = 16; o; o >>= 1) {
            v0 += __shfl_xor_sync(0xffffffffu, v0, o);
            v1 += __shfl_xor_sync(0xffffffffu, v1, o);
            v2 += __shfl_xor_sync(0xffffffffu, v2, o);
            v3 += __shfl_xor_sync(0xffffffffu, v3, o);
        }
        if (lane == 0) {
            wpart[sP][w & 3][0] = v0; wpart[sP][w & 3][1] = v1;
            wpart[sP][w & 3][2] = v2; wpart[sP][w & 3][3] = v3;
        }
        __syncthreads();
        if (tid < 8) {
            int pr = tid >> 2, q = tid & 3;
            float sm = wpart[pr][0][q] + wpart[pr][1][q] + wpart[pr][2][q] + wpart[pr][3][q];
            int pp = p + pr;
            if (q == 0)      cs0[2 * pp]     += sm;
            else if (q == 1) cs0[2 * pp + 1] += sm;
            else if (q == 2) cs1[2 * pp]     += sm;
            else             cs1[2 * pp + 1] += sm;
        }
        __syncthreads();
    }
    const float scale = 1.f / (1024.f * 512.f);
    if (tid < 128) {
        g_chunk[((size_t)b * NF + 2 * seg) * DM + tid]     = cs0[tid] * scale;
        g_chunk[((size_t)b * NF + 2 * seg + 1) * DM + tid] = cs1[tid] * scale;
    }
}

// ---------------- frames + pos-encoding + embed (8 rows / block) -------------
__global__ __launch_bounds__(128) void embed_kernel(const float* __restrict__ eb)
{
    const int row0 = blockIdx.x << 3;
    const int tid = threadIdx.x;
    __shared__ float vec[8][161];
    for (int idx = tid; idx < 1024; idx += 128) {
        int r = idx >> 7, ch = idx & 127;
        int row = row0 + r, t = row & 127;
        float f = g_chunk[(size_t)row * DM + ch];
        if (t > 0) f += g_chunk[(size_t)(row - 1) * DM + ch];
        vec[r][ch] = f;
    }
    for (int idx = tid; idx < 264; idx += 128) {
        int r = idx / 33, kk = idx % 33;
        int t = (row0 + r) & 127;
        float pos = (t == 127) ? 1.0f
                               : __fadd_rn(-1.0f, __fmul_rn((float)t, __fdiv_rn(2.0f, 127.0f)));
        float v;
        if (kk == 0) v = pos;
        else {
            int k = (kk <= 16) ? (kk - 1) : (kk - 17);
            float fr = __fmul_rn(exp2f((float)k), 3.14159274101257324f);
            float prod = __fmul_rn(pos, fr);
            v = (kk <= 16) ? (float)sin((double)prod) : (float)cos((double)prod);
        }
        vec[r][128 + kk] = v;
    }
    __syncthreads();
    float acc[8];
    float bv = eb[tid];
#pragma unroll
    for (int r = 0; r < 8; r++) acc[r] = bv;
    for (int j = 0; j < 161; j++) {
        float wv = g_ewT[j * 128 + tid];
#pragma unroll
        for (int r = 0; r < 8; r++) acc[r] = fmaf(vec[r][j], wv, acc[r]);
    }
#pragma unroll
    for (int r = 0; r < 8; r++)
        g_h[(size_t)(row0 + r) * DM + tid] = acc[r];
}

// ---------------- fused qkv + attention, one CTA per (head, batch) -----------
#define QA_SMEM (24576 * 4)   // hs 16384 + ks 4096 + vs 4096 floats
__global__ __launch_bounds__(128) void qkv_attn_kernel(const float* __restrict__ h,
                                                       const float* __restrict__ W,
                                                       const float* __restrict__ bias)
{
    extern __shared__ __align__(16) float qa[];
    float* hs = qa;            // [128][128]
    float* ks = qa + 16384;    // [128][32]
    float* vs = qa + 20480;    // [128][32]
    const int hd = blockIdx.x, b = blockIdx.y;
    const int tid = threadIdx.x;

    const float4* hsrc = (const float4*)(h + (size_t)b * NF * DM);
    float4* hs4 = (float4*)hs;
    for (int i = tid; i < 4096; i += 128) hs4[i] = hsrc[i];
    __syncthreads();

    const float4* hrow = (const float4*)(hs + tid * DM);
    const float4* wqp = (const float4*)(W + (size_t)(hd * 32) * DM);
    const float4* wkp = (const float4*)(W + (size_t)(128 + hd * 32) * DM);
    const float4* wvp = (const float4*)(W + (size_t)(256 + hd * 32) * DM);

    float acc[32];
    // ---- k ----
#pragma unroll
    for (int i = 0; i < 32; i++) acc[i] = __ldg(bias + 128 + hd * 32 + i);
    for (int d4 = 0; d4 < 32; d4++) {
        float4 hv = hrow[d4];
#pragma unroll
        for (int i = 0; i < 32; i++) {
            float4 wv4 = __ldg(wkp + i * 32 + d4);
            acc[i] = fmaf(hv.x, wv4.x, acc[i]);
            acc[i] = fmaf(hv.y, wv4.y, acc[i]);
            acc[i] = fmaf(hv.z, wv4.z, acc[i]);
            acc[i] = fmaf(hv.w, wv4.w, acc[i]);
        }
    }
#pragma unroll
    for (int i = 0; i < 32; i++) ks[tid * 32 + i] = acc[i];
    // ---- v ----
#pragma unroll
    for (int i = 0; i < 32; i++) acc[i] = __ldg(bias + 256 + hd * 32 + i);
    for (int d4 = 0; d4 < 32; d4++) {
        float4 hv = hrow[d4];
#pragma unroll
        for (int i = 0; i < 32; i++) {
            float4 wv4 = __ldg(wvp + i * 32 + d4);
            acc[i] = fmaf(hv.x, wv4.x, acc[i]);
            acc[i] = fmaf(hv.y, wv4.y, acc[i]);
            acc[i] = fmaf(hv.z, wv4.z, acc[i]);
            acc[i] = fmaf(hv.w, wv4.w, acc[i]);
        }
    }
#pragma unroll
    for (int i = 0; i < 32; i++) vs[tid * 32 + i] = acc[i];
    // ---- q (stays in regs) ----
#pragma unroll
    for (int i = 0; i < 32; i++) acc[i] = __ldg(bias + hd * 32 + i);
    for (int d4 = 0; d4 < 32; d4++) {
        float4 hv = hrow[d4];
#pragma unroll
        for (int i = 0; i < 32; i++) {
            float4 wv4 = __ldg(wqp + i * 32 + d4);
            acc[i] = fmaf(hv.x, wv4.x, acc[i]);
            acc[i] = fmaf(hv.y, wv4.y, acc[i]);
            acc[i] = fmaf(hv.z, wv4.z, acc[i]);
            acc[i] = fmaf(hv.w, wv4.w, acc[i]);
        }
    }
    __syncthreads();

    // ---- flash over 128 keys (j-unroll 2) ----
    float o[32];
#pragma unroll
    for (int i = 0; i < 32; i++) o[i] = 0.f;
    float m = -FLT_MAX, l = 0.f;
    const float scale = 0.17677669529663689f;

    for (int j = 0; j < NF; j += 2) {
        const float4* kp1 = (const float4*)(ks + j * 32);
        const float4* kp2 = (const float4*)(ks + j * 32 + 32);
        float s1 = 0.f, s2 = 0.f;
#pragma unroll
        for (int i = 0; i < 8; i++) {
            float4 k1 = kp1[i], k2 = kp2[i];
            s1 = fmaf(acc[4 * i], k1.x, s1); s2 = fmaf(acc[4 * i], k2.x, s2);
            s1 = fmaf(acc[4 * i + 1], k1.y, s1); s2 = fmaf(acc[4 * i + 1], k2.y, s2);
            s1 = fmaf(acc[4 * i + 2], k1.z, s1); s2 = fmaf(acc[4 * i + 2], k2.z, s2);
            s1 = fmaf(acc[4 * i + 3], k1.w, s1); s2 = fmaf(acc[4 * i + 3], k2.w, s2);
        }
        s1 *= scale; s2 *= scale;
        float mn = fmaxf(m, fmaxf(s1, s2));
        float c = expf(m - mn);
        float p1 = expf(s1 - mn);
        float p2 = expf(s2 - mn);
        l = l * c + p1 + p2;
        const float4* vp1 = (const float4*)(vs + j * 32);
        const float4* vp2 = (const float4*)(vs + j * 32 + 32);
#pragma unroll
        for (int i = 0; i < 8; i++) {
            float4 v1 = vp1[i], v2 = vp2[i];
            o[4 * i]     = fmaf(p2, v2.x, fmaf(p1, v1.x, o[4 * i] * c));
            o[4 * i + 1] = fmaf(p2, v2.y, fmaf(p1, v1.y, o[4 * i + 1] * c));
            o[4 * i + 2] = fmaf(p2, v2.z, fmaf(p1, v1.z, o[4 * i + 2] * c));
            o[4 * i + 3] = fmaf(p2, v2.w, fmaf(p1, v1.w, o[4 * i + 3] * c));
        }
        m = mn;
    }
    float inv = 1.f / l;
    float* dst = g_attno + (size_t)(b * NF + tid) * DM + hd * 32;
#pragma unroll
    for (int i = 0; i < 32; i++) dst[i] = o[i] * inv;
}

// ---------------- LN epilogues ------------------------------------------------
__device__ __forceinline__ void ln_to_gmem(float v[8], const float* lnw, const float* lnb,
                                           float* h, int row0, int tid)
{
    __shared__ float red[4][8];
    const int w = tid >> 5;
    float mean[8];
#pragma unroll
    for (int r = 0; r < 8; r++) {
        float s = v[r];
#pragma unroll
        for (int o = 16; o; o >>= 1) s += __shfl_xor_sync(0xffffffffu, s, o);
        if ((tid & 31) == 0) red[w][r] = s;
    }
    __syncthreads();
#pragma unroll
    for (int r = 0; r < 8; r++)
        mean[r] = (red[0][r] + red[1][r] + red[2][r] + red[3][r]) * 0.0078125f;
    __syncthreads();
#pragma unroll
    for (int r = 0; r < 8; r++) {
        float dv = v[r] - mean[r];
        float s = dv * dv;
#pragma unroll
        for (int o = 16; o; o >>= 1) s += __shfl_xor_sync(0xffffffffu, s, o);
        if ((tid & 31) == 0) red[w][r] = s;
        v[r] = dv;
    }
    __syncthreads();
    float lw = lnw[tid], lb = lnb[tid];
#pragma unroll
    for (int r = 0; r < 8; r++) {
        float var = (red[0][r] + red[1][r] + red[2][r] + red[3][r]) * 0.0078125f;
        h[(size_t)(row0 + r) * DM + tid] = v[r] * (1.f / sqrtf(var + 1e-5f)) * lw + lb;
    }
}

__device__ __forceinline__ void ln_to_smem(float v[8], const float* lnw, const float* lnb,
                                           float* dst, int tid)
{
    __shared__ float red2[4][8];
    const int w = tid >> 5;
    float mean[8];
#pragma unroll
    for (int r = 0; r < 8; r++) {
        float s = v[r];
#pragma unroll
        for (int o = 16; o; o >>= 1) s += __shfl_xor_sync(0xffffffffu, s, o);
        if ((tid & 31) == 0) red2[w][r] = s;
    }
    __syncthreads();
#pragma unroll
    for (int r = 0; r < 8; r++)
        mean[r] = (red2[0][r] + red2[1][r] + red2[2][r] + red2[3][r]) * 0.0078125f;
    __syncthreads();
#pragma unroll
    for (int r = 0; r < 8; r++) {
        float dv = v[r] - mean[r];
        float s = dv * dv;
#pragma unroll
        for (int o = 16; o; o >>= 1) s += __shfl_xor_sync(0xffffffffu, s, o);
        if ((tid & 31) == 0) red2[w][r] = s;
        v[r] = dv;
    }
    __syncthreads();
    float lw = lnw[tid], lb = lnb[tid];
#pragma unroll
    for (int r = 0; r < 8; r++) {
        float var = (red2[0][r] + red2[1][r] + red2[2][r] + red2[3][r]) * 0.0078125f;
        dst[r * DM + tid] = v[r] * (1.f / sqrtf(var + 1e-5f)) * lw + lb;
    }
}

// ---------------- post: proj + res + LN1 + FFN + res + LN2 -------------------
__global__ __launch_bounds__(128) void post_kernel(const float* __restrict__ in,
                                                   const float* __restrict__ Wo,
                                                   const float* __restrict__ bo,
                                                   const float* __restrict__ ln1w,
                                                   const float* __restrict__ ln1b,
                                                   const float* __restrict__ W1,
                                                   const float* __restrict__ b1,
                                                   const float* __restrict__ W2,
                                                   const float* __restrict__ b2,
                                                   const float* __restrict__ ln2w,
                                                   const float* __restrict__ ln2b,
                                                   float* __restrict__ h)
{
    const int row0 = blockIdx.x << 3;
    const int tid = threadIdx.x;
    __shared__ __align__(16) float sv[8 * DM];
    __shared__ __align__(16) float s1[8 * DM];
#pragma unroll
    for (int r = 0; r < 8; r++) sv[r * DM + tid] = in[(size_t)(row0 + r) * DM + tid];
    __syncthreads();

    float acc[8];
    // proj
    {
        float bv = bo[tid];
#pragma unroll
        for (int r = 0; r < 8; r++) acc[r] = bv;
        const float4* sv4 = (const float4*)sv;
        const float4* W4 = (const float4*)Wo;
        for (int j4 = 0; j4 < 32; j4++) {
            float4 wv = W4[(size_t)tid * 32 + j4];
#pragma unroll
            for (int r = 0; r < 8; r++) {
                float4 xv = sv4[r * 32 + j4];
                acc[r] = fmaf(wv.x, xv.x, acc[r]);
                acc[r] = fmaf(wv.y, xv.y, acc[r]);
                acc[r] = fmaf(wv.z, xv.z, acc[r]);
                acc[r] = fmaf(wv.w, xv.w, acc[r]);
            }
        }
    }
    float v[8];
#pragma unroll
    for (int r = 0; r < 8; r++) v[r] = h[(size_t)(row0 + r) * DM + tid] + acc[r];
    // LN1 -> sv (safe: epilogue syncs before writes)
    ln_to_smem(v, ln1w, ln1b, sv, tid);
    __syncthreads();
    // FFN lin1 + relu
    {
        float bv = b1[tid];
#pragma unroll
        for (int r = 0; r < 8; r++) acc[r] = bv;
        const float4* sv4 = (const float4*)sv;
        const float4* W4 = (const float4*)W1;
        for (int j4 = 0; j4 < 32; j4++) {
            float4 wv = W4[(size_t)tid * 32 + j4];
#pragma unroll
            for (int r = 0; r < 8; r++) {
                float4 xv = sv4[r * 32 + j4];
                acc[r] = fmaf(wv.x, xv.x, acc[r]);
                acc[r] = fmaf(wv.y, xv.y, acc[r]);
                acc[r] = fmaf(wv.z, xv.z, acc[r]);
                acc[r] = fmaf(wv.w, xv.w, acc[r]);
            }
        }
    }
#pragma unroll
    for (int r = 0; r < 8; r++) s1[r * DM + tid] = fmaxf(acc[r], 0.f);
    __syncthreads();
    // FFN lin2
    {
        float bv = b2[tid];
#pragma unroll
        for (int r = 0; r < 8; r++) acc[r] = bv;
        const float4* s14 = (const float4*)s1;
        const float4* W4 = (const float4*)W2;
        for (int j4 = 0; j4 < 32; j4++) {
            float4 wv = W4[(size_t)tid * 32 + j4];
#pragma unroll
            for (int r = 0; r < 8; r++) {
                float4 xv = s14[r * 32 + j4];
                acc[r] = fmaf(wv.x, xv.x, acc[r]);
                acc[r] = fmaf(wv.y, xv.y, acc[r]);
                acc[r] = fmaf(wv.z, xv.z, acc[r]);
                acc[r] = fmaf(wv.w, xv.w, acc[r]);
            }
        }
    }
#pragma unroll
    for (int r = 0; r < 8; r++) v[r] = sv[r * DM + tid] + acc[r];
    ln_to_gmem(v, ln2w, ln2b, h, row0, tid);
}

// ---------------- attention scores + top-16 ---------------------------------
__global__ __launch_bounds__(128) void topk_kernel(const float* __restrict__ attn_w,
                                                   const float* __restrict__ attn_b)
{
    const int b = blockIdx.x, tid = threadIdx.x;
    __shared__ float sv[128];
    __shared__ float rv[128];
    __shared__ int ri[128];
    const float4* hp = (const float4*)(g_h + (size_t)(b * NF + tid) * DM);
    const float4* wp = (const float4*)attn_w;
    float s = attn_b[0];
#pragma unroll
    for (int i = 0; i < 32; i++) {
        float4 h4 = hp[i], w4 = wp[i];
        s = fmaf(h4.x, w4.x, s); s = fmaf(h4.y, w4.y, s);
        s = fmaf(h4.z, w4.z, s); s = fmaf(h4.w, w4.w, s);
    }
    sv[tid] = s;
    __syncthreads();
    for (int r = 0; r < 16; r++) {
        rv[tid] = sv[tid]; ri[tid] = tid;
        __syncthreads();
        for (int off = 64; off; off >>= 1) {
            if (tid < off) {
                float v2 = rv[tid + off]; int i2 = ri[tid + off];
                if (v2 > rv[tid] || (v2 == rv[tid] && i2 < ri[tid])) { rv[tid] = v2; ri[tid] = i2; }
            }
            __syncthreads();
        }
        if (tid == 0) {
            g_topidx[b * 16 + r] = ri[0];
            g_topval[b * 16 + r] = rv[0];
            sv[ri[0]] = -FLT_MAX;
        }
        __syncthreads();
    }
}

// ---------------- head: amp, pos/atom argmax, scatter -----------------------
__global__ __launch_bounds__(128) void scatter_kernel(const float* __restrict__ amp_w,
                                                      const float* __restrict__ amp_b,
                                                      const float* __restrict__ pos_w,
                                                      const float* __restrict__ pos_b,
                                                      const float* __restrict__ atom_w,
                                                      const float* __restrict__ atom_b,
                                                      const float* __restrict__ dmat,
                                                      float* __restrict__ out)
{
    const int rk = blockIdx.x, b = blockIdx.y, tid = threadIdx.x;
    __shared__ __align__(16) float vec[128];
    __shared__ float rv[128];
    __shared__ int ri[128];
    __shared__ float amp_s;
    __shared__ int jstar_s, astar_s;

    int id = g_topidx[b * 16 + rk];
    float val = g_topval[b * 16 + rk];
    vec[tid] = g_h[(size_t)(b * NF + id) * DM + tid] * val;
    __syncthreads();

    rv[tid] = vec[tid] * amp_w[tid];
    __syncthreads();
    for (int off = 64; off; off >>= 1) {
        if (tid < off) rv[tid] += rv[tid + off];
        __syncthreads();
    }
    if (tid == 0) amp_s = fmaxf(rv[0] + amp_b[0], 0.f);
    __syncthreads();

    const float4* vp = (const float4*)vec;

    float bv = -FLT_MAX; int bi = 1 << 30;
#pragma unroll
    for (int q = 0; q < 4; q++) {
        int o = q * 128 + tid;
        const float4* wp = (const float4*)(pos_w + (size_t)o * DM);
        float lg = pos_b[o];
#pragma unroll
        for (int i = 0; i < 32; i++) {
            float4 w4 = wp[i], v4 = vp[i];
            lg = fmaf(w4.x, v4.x, lg); lg = fmaf(w4.y, v4.y, lg);
            lg = fmaf(w4.z, v4.z, lg); lg = fmaf(w4.w, v4.w, lg);
        }
        if (lg > bv || (lg == bv && o < bi)) { bv = lg; bi = o; }
    }
    rv[tid] = bv; ri[tid] = bi;
    __syncthreads();
    for (int off = 64; off; off >>= 1) {
        if (tid < off) {
            float v2 = rv[tid + off]; int i2 = ri[tid + off];
            if (v2 > rv[tid] || (v2 == rv[tid] && i2 < ri[tid])) { rv[tid] = v2; ri[tid] = i2; }
        }
        __syncthreads();
    }
    if (tid == 0) jstar_s = ri[0];
    __syncthreads();

    bv = -FLT_MAX; bi = 1 << 30;
#pragma unroll
    for (int q = 0; q < 2; q++) {
        int o = q * 128 + tid;
        const float4* wp = (const float4*)(atom_w + (size_t)o * DM);
        float lg = atom_b[o];
#pragma unroll
        for (int i = 0; i < 32; i++) {
            float4 w4 = wp[i], v4 = vp[i];
            lg = fmaf(w4.x, v4.x, lg); lg = fmaf(w4.y, v4.y, lg);
            lg = fmaf(w4.z, v4.z, lg); lg = fmaf(w4.w, v4.w, lg);
        }
        if (lg > bv || (lg == bv && o < bi)) { bv = lg; bi = o; }
    }
    rv[tid] = bv; ri[tid] = bi;
    __syncthreads();
    for (int off = 64; off; off >>= 1) {
        if (tid < off) {
            float v2 = rv[tid + off]; int i2 = ri[tid + off];
            if (v2 > rv[tid] || (v2 == rv[tid] && i2 < ri[tid])) { rv[tid] = v2; ri[tid] = i2; }
        }
        __syncthreads();
    }
    if (tid == 0) astar_s = ri[0];
    __syncthreads();

    float amp = amp_s;
    int p = jstar_s * 64;
    int a = astar_s;
    for (int i = tid; i < 256; i += 128) {
        int t = p + i;
        if (t < NS)
            atomicAdd(out + (size_t)b * NS + t, dmat[(size_t)a * 256 + i] * amp);
    }
}

// ---------------------------------------------------------------------------
extern "C" void kernel_launch(void* const* d_in, const int* in_sizes, int n_in,
                              void* d_out, int out_size)
{
    const float* x         = (const float*)d_in[0];
    const float* fb        = (const float*)d_in[1];
    const float* embed_w   = (const float*)d_in[2];
    const float* embed_b   = (const float*)d_in[3];
    const float* in_proj_w = (const float*)d_in[4];
    const float* in_proj_b = (const float*)d_in[5];
    const float* out_w     = (const float*)d_in[6];
    const float* out_b     = (const float*)d_in[7];
    const float* lin1_w    = (const float*)d_in[8];
    const float* lin1_b    = (const float*)d_in[9];
    const float* lin2_w    = (const float*)d_in[10];
    const float* lin2_b    = (const float*)d_in[11];
    const float* ln1_w     = (const float*)d_in[12];
    const float* ln1_b     = (const float*)d_in[13];
    const float* ln2_w     = (const float*)d_in[14];
    const float* ln2_b     = (const float*)d_in[15];
    const float* attn_w    = (const float*)d_in[16];
    const float* attn_b    = (const float*)d_in[17];
    const float* amp_w     = (const float*)d_in[18];
    const float* amp_b     = (const float*)d_in[19];
    const float* pos_w     = (const float*)d_in[20];
    const float* pos_b     = (const float*)d_in[21];
    const float* atom_w    = (const float*)d_in[22];
    const float* atom_b    = (const float*)d_in[23];
    const float* dmat      = (const float*)d_in[24];
    float* out = (float*)d_out;

    float *p_h, *p_attno;
    cudaGetSymbolAddress((void**)&p_h, g_h);
    cudaGetSymbolAddress((void**)&p_attno, g_attno);

    cudaFuncSetAttribute(qkv_attn_kernel, cudaFuncAttributeMaxDynamicSharedMemorySize, QA_SMEM);

    twid_kernel<<<2, 256>>>();
    ewt_kernel<<<(161 * 128 + 255) / 256, 256>>>(embed_w);
    filt_kernel<<<64, 256>>>(fb);
    conv_fft_kernel<<<dim3(64, NB), 256>>>(x);

    embed_kernel<<<NB * NF / 8, 128>>>(embed_b);

    for (int i = 0; i < 6; i++) {
        qkv_attn_kernel<<<dim3(4, NB), 128, QA_SMEM>>>(p_h,
                                                       in_proj_w + (size_t)i * 384 * 128,
                                                       in_proj_b + i * 384);
        post_kernel<<<512, 128>>>(p_attno,
                                  out_w + (size_t)i * 128 * 128, out_b + i * 128,
                                  ln1_w + i * 128, ln1_b + i * 128,
                                  lin1_w + (size_t)i * 128 * 128, lin1_b + i * 128,
                                  lin2_w + (size_t)i * 128 * 128, lin2_b + i * 128,
                                  ln2_w + i * 128, ln2_b + i * 128, p_h);
    }

    topk_kernel<<<NB, 128>>>(attn_w, attn_b);
    cudaMemsetAsync(d_out, 0, (size_t)out_size * sizeof(float), 0);
    scatter_kernel<<<dim3(16, NB), 128>>>(amp_w, amp_b, pos_w, pos_b,
                                          atom_w, atom_b, dmat, out);
}

// round 12
// speedup vs baseline: 1.1119x; 1.1119x over previous
#include <cuda_runtime.h>
#include <math.h>
#include <float.h>

#define NB 32
#define NS 32768
#define NF 128
#define DM 128

// ------------------------- scratch (device globals) -------------------------
__device__ float2 g_twid[512];            // exp(-2*pi*i*k/1024)
__device__ float2 g_P[64 * 1024];         // conj(FFT(w_2c - i w_2c+1)), scrambled
__device__ float g_ewT[161 * 128];        // transposed embed weights
__device__ float g_chunk[NB * NF * DM];
__device__ float g_h[NB * NF * DM];
__device__ float g_qkv[NB * NF * 384];
__device__ float g_attno[NB * NF * DM];
__device__ int   g_topidx[NB * 16];
__device__ float g_topval[NB * 16];

// ------------------------- butterflies ---------------------------------------
__device__ __forceinline__ void bf_dif(float& ar, float& ai, float& br, float& bi, float2 w)
{
    float xr = ar - br, xi = ai - bi;
    ar += br; ai += bi;
    br = xr * w.x - xi * w.y;
    bi = xr * w.y + xi * w.x;
}
__device__ __forceinline__ void bf_dit(float& ar, float& ai, float& br, float& bi, float2 w)
{
    float tr = br * w.x + bi * w.y;
    float ti = bi * w.x - br * w.y;
    br = ar - tr; bi = ai - ti;
    ar += tr; ai += ti;
}

// ------------------------- forward 1024-pt DIF (in-place, natural->bitrev) ---
__device__ __forceinline__ void fft1024_dif(float* re, float* im, const float2* tw, int tid)
{
    {   // stages h=512, 256
        int r = tid;
        float ar = re[r],       ai = im[r];
        float br = re[r + 256], bi = im[r + 256];
        float cr = re[r + 512], ci = im[r + 512];
        float dr = re[r + 768], di = im[r + 768];
        bf_dif(ar, ai, cr, ci, tw[r]);
        bf_dif(br, bi, dr, di, tw[r + 256]);
        float2 v = tw[2 * r];
        bf_dif(ar, ai, br, bi, v);
        bf_dif(cr, ci, dr, di, v);
        re[r] = ar;       im[r] = ai;
        re[r + 256] = br; im[r + 256] = bi;
        re[r + 512] = cr; im[r + 512] = ci;
        re[r + 768] = dr; im[r + 768] = di;
    }
    __syncthreads();
    {   // stages h=128, 64
        int q = tid >> 6, r = tid & 63, i0 = q * 256 + r;
        float ar = re[i0],       ai = im[i0];
        float br = re[i0 + 64],  bi = im[i0 + 64];
        float cr = re[i0 + 128], ci = im[i0 + 128];
        float dr = re[i0 + 192], di = im[i0 + 192];
        bf_dif(ar, ai, cr, ci, tw[4 * r]);
        bf_dif(br, bi, dr, di, tw[4 * r + 256]);
        float2 v = tw[8 * r];
        bf_dif(ar, ai, br, bi, v);
        bf_dif(cr, ci, dr, di, v);
        re[i0] = ar;       im[i0] = ai;
        re[i0 + 64] = br;  im[i0 + 64] = bi;
        re[i0 + 128] = cr; im[i0 + 128] = ci;
        re[i0 + 192] = dr; im[i0 + 192] = di;
    }
    __syncthreads();
    {   // stages h=32..4 (shuffle), 2,1 (in-thread)
        float4 R = ((const float4*)re)[tid];
        float4 I = ((const float4*)im)[tid];
        float vr[4] = {R.x, R.y, R.z, R.w};
        float vi[4] = {I.x, I.y, I.z, I.w};
#pragma unroll
        for (int s = 3; s >= 0; s--) {
            const int mask = 1 << s;
            const int step = 128 >> s;
            const int kb = 4 * (tid & (mask - 1));
            const bool up = (tid & mask) != 0;
#pragma unroll
            for (int j = 0; j < 4; j++) {
                float orr = __shfl_xor_sync(0xffffffffu, vr[j], mask);
                float oii = __shfl_xor_sync(0xffffffffu, vi[j], mask);
                float2 w = tw[(kb + j) * step];
                float sr = vr[j] + orr, si = vi[j] + oii;
                float dr = orr - vr[j], di = oii - vi[j];
                float pr = dr * w.x - di * w.y;
                float pi = dr * w.y + di * w.x;
                vr[j] = up ? pr : sr;
                vi[j] = up ? pi : si;
            }
        }
        {
            float s0r = vr[0] + vr[2], s0i = vi[0] + vi[2];
            float d0r = vr[0] - vr[2], d0i = vi[0] - vi[2];
            vr[0] = s0r; vi[0] = s0i; vr[2] = d0r; vi[2] = d0i;
            float s1r = vr[1] + vr[3], s1i = vi[1] + vi[3];
            float d1r = vr[1] - vr[3], d1i = vi[1] - vi[3];
            vr[1] = s1r; vi[1] = s1i;
            vr[3] = d1i; vi[3] = -d1r;
        }
        {
            float t0r = vr[0] + vr[1], t0i = vi[0] + vi[1];
            float t1r = vr[0] - vr[1], t1i = vi[0] - vi[1];
            float t2r = vr[2] + vr[3], t2i = vi[2] + vi[3];
            float t3r = vr[2] - vr[3], t3i = vi[2] - vi[3];
            vr[0] = t0r; vi[0] = t0i; vr[1] = t1r; vi[1] = t1i;
            vr[2] = t2r; vi[2] = t2i; vr[3] = t3r; vi[3] = t3i;
        }
        ((float4*)re)[tid] = make_float4(vr[0], vr[1], vr[2], vr[3]);
        ((float4*)im)[tid] = make_float4(vi[0], vi[1], vi[2], vi[3]);
    }
    __syncthreads();
}

// ------------------------- precompute kernels --------------------------------
__global__ void twid_kernel()
{
    int k = blockIdx.x * 256 + threadIdx.x;
    if (k < 512) {
        double a = -2.0 * 3.14159265358979323846 * (double)k / 1024.0;
        g_twid[k] = make_float2((float)cos(a), (float)sin(a));
    }
}

__global__ __launch_bounds__(256) void filt_kernel(const float* __restrict__ fb)
{
    __shared__ __align__(16) float re[1024], im[1024];
    __shared__ __align__(16) float2 tw[512];
    const int c = blockIdx.x, tid = threadIdx.x;
    tw[tid] = g_twid[tid]; tw[tid + 256] = g_twid[tid + 256];
    for (int i = tid; i < 1024; i += 256) {
        re[i] = (i < 512) ? fb[(size_t)(2 * c) * 512 + i] : 0.f;
        im[i] = (i < 512) ? -fb[(size_t)(2 * c + 1) * 512 + i] : 0.f;
    }
    __syncthreads();
    fft1024_dif(re, im, tw, tid);
    for (int i = tid; i < 1024; i += 256)
        g_P[(size_t)c * 1024 + i] = make_float2(re[i], -im[i]);
}

__global__ void ewt_kernel(const float* __restrict__ ew)
{
    int i = blockIdx.x * 256 + threadIdx.x;
    if (i < 161 * 128) {
        int j = i >> 7, c = i & 127;
        g_ewT[j * 128 + c] = ew[(size_t)c * 161 + j];
    }
}

// ---- trip A: fused pointwise(U*P) + DIT stages 1..64; result to z slot -------
__device__ __forceinline__ void ifft_stageA(const float ur[4], const float ui[4],
                                            const float4* __restrict__ Pp,
                                            const float2* twA, int tid,
                                            float* zr, float* zi)
{
    float4 P0 = Pp[2 * tid], P1 = Pp[2 * tid + 1];
    float vr[4], vi[4];
    vr[0] = ur[0] * P0.x - ui[0] * P0.y; vi[0] = ur[0] * P0.y + ui[0] * P0.x;
    vr[1] = ur[1] * P0.z - ui[1] * P0.w; vi[1] = ur[1] * P0.w + ui[1] * P0.z;
    vr[2] = ur[2] * P1.x - ui[2] * P1.y; vi[2] = ur[2] * P1.y + ui[2] * P1.x;
    vr[3] = ur[3] * P1.z - ui[3] * P1.w; vi[3] = ur[3] * P1.w + ui[3] * P1.z;
    {   // h=1 (Wc=1)
        float t0r = vr[0] + vr[1], t0i = vi[0] + vi[1];
        float t1r = vr[0] - vr[1], t1i = vi[0] - vi[1];
        float t2r = vr[2] + vr[3], t2i = vi[2] + vi[3];
        float t3r = vr[2] - vr[3], t3i = vi[2] - vi[3];
        vr[0] = t0r; vi[0] = t0i; vr[1] = t1r; vi[1] = t1i;
        vr[2] = t2r; vi[2] = t2i; vr[3] = t3r; vi[3] = t3i;
    }
    {   // h=2: (0,2) Wc=1; (1,3) Wc=(0,1)
        float s0r = vr[0] + vr[2], s0i = vi[0] + vi[2];
        float d0r = vr[0] - vr[2], d0i = vi[0] - vi[2];
        vr[0] = s0r; vi[0] = s0i; vr[2] = d0r; vi[2] = d0i;
        float tr = -vi[3], ti = vr[3];
        float nr = vr[1] + tr, ni = vi[1] + ti;
        float mr = vr[1] - tr, mi = vi[1] - ti;
        vr[1] = nr; vi[1] = ni; vr[3] = mr; vi[3] = mi;
    }
#pragma unroll
    for (int s = 0; s < 5; s++) {               // h = 4,8,16,32,64
        const int mask = 1 << s;
        const int offA = 4 * (mask - 1);
        const int ib = tid & (mask - 1);
#pragma unroll
        for (int j = 0; j < 4; j++) {
            float orr = __shfl_xor_sync(0xffffffffu, vr[j], mask);
            float oii = __shfl_xor_sync(0xffffffffu, vi[j], mask);
            float2 tww = twA[offA + (j << s) + ib];
            const bool up = (tid & mask) != 0;
            float sr = up ? vr[j] : orr;
            float sI = up ? vi[j] : oii;
            float tr = sr * tww.x + sI * tww.y;
            float ti = sI * tww.x - sr * tww.y;
            float lr = vr[j] + tr, li = vi[j] + ti;
            float ur_ = orr - tr, ui_ = oii - ti;
            vr[j] = up ? ur_ : lr;
            vi[j] = up ? ui_ : li;
        }
    }
    ((float4*)zr)[tid] = make_float4(vr[0], vr[1], vr[2], vr[3]);
    ((float4*)zi)[tid] = make_float4(vi[0], vi[1], vi[2], vi[3]);
}

// ------------------------- FFT conv + |.| + pool -----------------------------
// CTA (seg, b). Two channel-pairs per iteration; BC phase fully in registers.
__global__ __launch_bounds__(256) void conv_fft_kernel(const float* __restrict__ x)
{
    __shared__ __align__(16) float uRe[1024], uIm[1024];
    __shared__ __align__(16) float zRe[2048], zIm[2048];
    __shared__ __align__(16) float2 tw[512];
    __shared__ __align__(16) float2 twA[124];
    __shared__ float cs0[128], cs1[128];
    __shared__ float wpart[2][4][4];
    const int seg = blockIdx.x, b = blockIdx.y;
    const int tid = threadIdx.x, w = tid >> 5, lane = tid & 31;

    tw[tid] = g_twid[tid]; tw[tid + 256] = g_twid[tid + 256];
    if (tid < 124) {
        int e = tid, s, base0;
        if (e < 4)       { s = 0; base0 = 0; }
        else if (e < 12) { s = 1; base0 = 4; }
        else if (e < 28) { s = 2; base0 = 12; }
        else if (e < 60) { s = 3; base0 = 28; }
        else             { s = 4; base0 = 60; }
        int r = e - base0;
        int j = r >> s;
        int i = r & ((1 << s) - 1);
        twA[e] = g_twid[(4 * i + j) * (128 >> s)];
    }
    const float* xb = x + (size_t)b * NS;
    const int base = seg * 512 - 256;
    for (int i = tid; i < 1024; i += 256) {
        int g = base + i;
        uRe[i] = (g >= 0 && g < NS) ? xb[g] : 0.f;
        uIm[i] = 0.f;
    }
    if (tid < 128) { cs0[tid] = 0.f; cs1[tid] = 0.f; }
    __syncthreads();
    fft1024_dif(uRe, uIm, tw, tid);

    // hoist loop invariants
    float ur[4], ui[4];
    {
        float4 R = ((const float4*)uRe)[tid];
        float4 I = ((const float4*)uIm)[tid];
        ur[0] = R.x; ur[1] = R.y; ur[2] = R.z; ur[3] = R.w;
        ui[0] = I.x; ui[1] = I.y; ui[2] = I.z; ui[3] = I.w;
    }
    const int rB = tid & 127;
    const float2 t4r  = tw[4 * rB];
    const float2 t2r  = tw[2 * rB];
    const float2 t2r2 = tw[2 * rB + 256];
    const float2 t5a = tw[rB], t5b = tw[rB + 128], t5c = tw[rB + 256], t5d = tw[rB + 384];

    for (int p = 0; p < 64; p += 2) {
        ifft_stageA(ur, ui, (const float4*)(g_P + (size_t)p * 1024), twA, tid, zRe, zIm);
        ifft_stageA(ur, ui, (const float4*)(g_P + (size_t)(p + 1) * 1024), twA, tid,
                    zRe + 1024, zIm + 1024);
        __syncthreads();

        // phase BC in registers: pair s = tid>>7, row r = rB
        const int s = tid >> 7;
        const float* zr = zRe + (s << 10);
        const float* zi = zIm + (s << 10);
        float xr[8], xi[8];
#pragma unroll
        for (int k = 0; k < 8; k++) { xr[k] = zr[rB + (k << 7)]; xi[k] = zi[rB + (k << 7)]; }
        bf_dit(xr[0], xi[0], xr[1], xi[1], t4r);
        bf_dit(xr[2], xi[2], xr[3], xi[3], t4r);
        bf_dit(xr[4], xi[4], xr[5], xi[5], t4r);
        bf_dit(xr[6], xi[6], xr[7], xi[7], t4r);
        bf_dit(xr[0], xi[0], xr[2], xi[2], t2r);
        bf_dit(xr[1], xi[1], xr[3], xi[3], t2r2);
        bf_dit(xr[4], xi[4], xr[6], xi[6], t2r);
        bf_dit(xr[5], xi[5], xr[7], xi[7], t2r2);
        {
            float tr, ti;
            tr = xr[4] * t5a.x + xi[4] * t5a.y; ti = xi[4] * t5a.x - xr[4] * t5a.y;
            xr[0] += tr; xi[0] += ti;
            tr = xr[5] * t5b.x + xi[5] * t5b.y; ti = xi[5] * t5b.x - xr[5] * t5b.y;
            xr[1] += tr; xi[1] += ti;
            tr = xr[6] * t5c.x + xi[6] * t5c.y; ti = xi[6] * t5c.x - xr[6] * t5c.y;
            xr[2] += tr; xi[2] += ti;
            tr = xr[7] * t5d.x + xi[7] * t5d.y; ti = xi[7] * t5d.x - xr[7] * t5d.y;
            xr[3] += tr; xi[3] += ti;
        }
        float v0 = fabsf(xr[0]) + fabsf(xr[1]);
        float v1 = fabsf(xi[0]) + fabsf(xi[1]);
        float v2 = fabsf(xr[2]) + fabsf(xr[3]);
        float v3 = fabsf(xi[2]) + fabsf(xi[3]);
#pragma unroll
        for (int o = 16; o; o >>= 1) {
            v0 += __shfl_xor_sync(0xffffffffu, v0, o);
            v1 += __shfl_xor_sync(0xffffffffu, v1, o);
            v2 += __shfl_xor_sync(0xffffffffu, v2, o);
            v3 += __shfl_xor_sync(0xffffffffu, v3, o);
        }
        if (lane == 0) {
            wpart[s][w & 3][0] = v0; wpart[s][w & 3][1] = v1;
            wpart[s][w & 3][2] = v2; wpart[s][w & 3][3] = v3;
        }
        __syncthreads();
        if (tid < 8) {
            int pr = tid >> 2, q = tid & 3;
            float sm = wpart[pr][0][q] + wpart[pr][1][q] + wpart[pr][2][q] + wpart[pr][3][q];
            int pp = p + pr;
            if (q == 0)      cs0[2 * pp]     += sm;
            else if (q == 1) cs0[2 * pp + 1] += sm;
            else if (q == 2) cs1[2 * pp]     += sm;
            else             cs1[2 * pp + 1] += sm;
        }
        __syncthreads();
    }
    const float scale = 1.f / (1024.f * 512.f);
    if (tid < 128) {
        g_chunk[((size_t)b * NF + 2 * seg) * DM + tid]     = cs0[tid] * scale;
        g_chunk[((size_t)b * NF + 2 * seg + 1) * DM + tid] = cs1[tid] * scale;
    }
}

// ---------------- frames + pos-encoding + embed (8 rows / block) -------------
__global__ __launch_bounds__(128) void embed_kernel(const float* __restrict__ eb)
{
    const int row0 = blockIdx.x << 3;
    const int tid = threadIdx.x;
    __shared__ float vec[8][161];
    for (int idx = tid; idx < 1024; idx += 128) {
        int r = idx >> 7, ch = idx & 127;
        int row = row0 + r, t = row & 127;
        float f = g_chunk[(size_t)row * DM + ch];
        if (t > 0) f += g_chunk[(size_t)(row - 1) * DM + ch];
        vec[r][ch] = f;
    }
    for (int idx = tid; idx < 264; idx += 128) {
        int r = idx / 33, kk = idx % 33;
        int t = (row0 + r) & 127;
        float pos = (t == 127) ? 1.0f
                               : __fadd_rn(-1.0f, __fmul_rn((float)t, __fdiv_rn(2.0f, 127.0f)));
        float v;
        if (kk == 0) v = pos;
        else {
            int k = (kk <= 16) ? (kk - 1) : (kk - 17);
            float fr = __fmul_rn(exp2f((float)k), 3.14159274101257324f);
            float prod = __fmul_rn(pos, fr);
            v = (kk <= 16) ? (float)sin((double)prod) : (float)cos((double)prod);
        }
        vec[r][128 + kk] = v;
    }
    __syncthreads();
    float acc[8];
    float bv = eb[tid];
#pragma unroll
    for (int r = 0; r < 8; r++) acc[r] = bv;
    for (int j = 0; j < 161; j++) {
        float wv = g_ewT[j * 128 + tid];
#pragma unroll
        for (int r = 0; r < 8; r++) acc[r] = fmaf(vec[r][j], wv, acc[r]);
    }
#pragma unroll
    for (int r = 0; r < 8; r++)
        g_h[(size_t)(row0 + r) * DM + tid] = acc[r];
}

// ---------------- qkv linear (K = 128, NO = 3) -------------------------------
__global__ __launch_bounds__(128) void qkv_kernel(const float* __restrict__ in,
                                                  const float* __restrict__ W,
                                                  const float* __restrict__ bias,
                                                  float* __restrict__ out)
{
    const int row0 = blockIdx.x << 3;
    const int tid = threadIdx.x;
    __shared__ __align__(16) float sv[8 * DM];
#pragma unroll
    for (int r = 0; r < 8; r++) sv[r * DM + tid] = in[(size_t)(row0 + r) * DM + tid];
    __syncthreads();
    float acc[3][8];
#pragma unroll
    for (int o = 0; o < 3; o++) {
        float bv = bias[o * DM + tid];
#pragma unroll
        for (int r = 0; r < 8; r++) acc[o][r] = bv;
    }
    const float4* sv4 = (const float4*)sv;
    const float4* W4 = (const float4*)W;
    for (int j4 = 0; j4 < 32; j4++) {
        float4 wv[3];
#pragma unroll
        for (int o = 0; o < 3; o++) wv[o] = W4[(size_t)(o * DM + tid) * 32 + j4];
#pragma unroll
        for (int r = 0; r < 8; r++) {
            float4 xv = sv4[r * 32 + j4];
#pragma unroll
            for (int o = 0; o < 3; o++) {
                acc[o][r] = fmaf(wv[o].x, xv.x, acc[o][r]);
                acc[o][r] = fmaf(wv[o].y, xv.y, acc[o][r]);
                acc[o][r] = fmaf(wv[o].z, xv.z, acc[o][r]);
                acc[o][r] = fmaf(wv[o].w, xv.w, acc[o][r]);
            }
        }
    }
#pragma unroll
    for (int r = 0; r < 8; r++)
#pragma unroll
        for (int o = 0; o < 3; o++)
            out[(size_t)(row0 + r) * 384 + o * DM + tid] = acc[o][r];
}

// ---------------- attention (one block per (head, batch), j-unroll 2) --------
__global__ __launch_bounds__(128) void attn_kernel()
{
    const int hd = blockIdx.x, b = blockIdx.y;
    const int tid = threadIdx.x;
    __shared__ __align__(16) float ks[NF * 32];
    __shared__ __align__(16) float vs[NF * 32];
    const float* base = g_qkv + (size_t)b * NF * 384;

    for (int idx = tid; idx < NF * 32; idx += 128) {
        int j = idx >> 5, i = idx & 31;
        ks[idx] = base[j * 384 + 128 + hd * 32 + i];
        vs[idx] = base[j * 384 + 256 + hd * 32 + i];
    }
    float q[32];
    {
        const float4* qp = (const float4*)(base + (size_t)tid * 384 + hd * 32);
#pragma unroll
        for (int i = 0; i < 8; i++) {
            float4 v = qp[i];
            q[4 * i] = v.x; q[4 * i + 1] = v.y; q[4 * i + 2] = v.z; q[4 * i + 3] = v.w;
        }
    }
    __syncthreads();

    float o[32];
#pragma unroll
    for (int i = 0; i < 32; i++) o[i] = 0.f;
    float m = -FLT_MAX, l = 0.f;
    const float scale = 0.17677669529663689f;

    for (int j = 0; j < NF; j += 2) {
        const float4* kp1 = (const float4*)(ks + j * 32);
        const float4* kp2 = (const float4*)(ks + j * 32 + 32);
        float s1 = 0.f, s2 = 0.f;
#pragma unroll
        for (int i = 0; i < 8; i++) {
            float4 k1 = kp1[i], k2 = kp2[i];
            s1 = fmaf(q[4 * i], k1.x, s1); s2 = fmaf(q[4 * i], k2.x, s2);
            s1 = fmaf(q[4 * i + 1], k1.y, s1); s2 = fmaf(q[4 * i + 1], k2.y, s2);
            s1 = fmaf(q[4 * i + 2], k1.z, s1); s2 = fmaf(q[4 * i + 2], k2.z, s2);
            s1 = fmaf(q[4 * i + 3], k1.w, s1); s2 = fmaf(q[4 * i + 3], k2.w, s2);
        }
        s1 *= scale; s2 *= scale;
        float mn = fmaxf(m, fmaxf(s1, s2));
        float c = expf(m - mn);
        float p1 = expf(s1 - mn);
        float p2 = expf(s2 - mn);
        l = l * c + p1 + p2;
        const float4* vp1 = (const float4*)(vs + j * 32);
        const float4* vp2 = (const float4*)(vs + j * 32 + 32);
#pragma unroll
        for (int i = 0; i < 8; i++) {
            float4 v1 = vp1[i], v2 = vp2[i];
            o[4 * i]     = fmaf(p2, v2.x, fmaf(p1, v1.x, o[4 * i] * c));
            o[4 * i + 1] = fmaf(p2, v2.y, fmaf(p1, v1.y, o[4 * i + 1] * c));
            o[4 * i + 2] = fmaf(p2, v2.z, fmaf(p1, v1.z, o[4 * i + 2] * c));
            o[4 * i + 3] = fmaf(p2, v2.w, fmaf(p1, v1.w, o[4 * i + 3] * c));
        }
        m = mn;
    }
    float inv = 1.f / l;
    float* dst = g_attno + (size_t)(b * NF + tid) * DM + hd * 32;
#pragma unroll
    for (int i = 0; i < 32; i++) dst[i] = o[i] * inv;
}

// ---------------- LN epilogues ------------------------------------------------
__device__ __forceinline__ void ln_to_gmem(float v[8], const float* lnw, const float* lnb,
                                           float* h, int row0, int tid)
{
    __shared__ float red[4][8];
    const int w = tid >> 5;
    float mean[8];
#pragma unroll
    for (int r = 0; r < 8; r++) {
        float s = v[r];
#pragma unroll
        for (int o = 16; o; o >>= 1) s += __shfl_xor_sync(0xffffffffu, s, o);
        if ((tid & 31) == 0) red[w][r] = s;
    }
    __syncthreads();
#pragma unroll
    for (int r = 0; r < 8; r++)
        mean[r] = (red[0][r] + red[1][r] + red[2][r] + red[3][r]) * 0.0078125f;
    __syncthreads();
#pragma unroll
    for (int r = 0; r < 8; r++) {
        float dv = v[r] - mean[r];
        float s = dv * dv;
#pragma unroll
        for (int o = 16; o; o >>= 1) s += __shfl_xor_sync(0xffffffffu, s, o);
        if ((tid & 31) == 0) red[w][r] = s;
        v[r] = dv;
    }
    __syncthreads();
    float lw = lnw[tid], lb = lnb[tid];
#pragma unroll
    for (int r = 0; r < 8; r++) {
        float var = (red[0][r] + red[1][r] + red[2][r] + red[3][r]) * 0.0078125f;
        h[(size_t)(row0 + r) * DM + tid] = v[r] * (1.f / sqrtf(var + 1e-5f)) * lw + lb;
    }
}

__device__ __forceinline__ void ln_to_smem(float v[8], const float* lnw, const float* lnb,
                                           float* dst, int tid)
{
    __shared__ float red2[4][8];
    const int w = tid >> 5;
    float mean[8];
#pragma unroll
    for (int r = 0; r < 8; r++) {
        float s = v[r];
#pragma unroll
        for (int o = 16; o; o >>= 1) s += __shfl_xor_sync(0xffffffffu, s, o);
        if ((tid & 31) == 0) red2[w][r] = s;
    }
    __syncthreads();
#pragma unroll
    for (int r = 0; r < 8; r++)
        mean[r] = (red2[0][r] + red2[1][r] + red2[2][r] + red2[3][r]) * 0.0078125f;
    __syncthreads();
#pragma unroll
    for (int r = 0; r < 8; r++) {
        float dv = v[r] - mean[r];
        float s = dv * dv;
#pragma unroll
        for (int o = 16; o; o >>= 1) s += __shfl_xor_sync(0xffffffffu, s, o);
        if ((tid & 31) == 0) red2[w][r] = s;
        v[r] = dv;
    }
    __syncthreads();
    float lw = lnw[tid], lb = lnb[tid];
#pragma unroll
    for (int r = 0; r < 8; r++) {
        float var = (red2[0][r] + red2[1][r] + red2[2][r] + red2[3][r]) * 0.0078125f;
        dst[r * DM + tid] = v[r] * (1.f / sqrtf(var + 1e-5f)) * lw + lb;
    }
}

// ---------------- post: proj + res + LN1 + FFN + res + LN2 -------------------
__global__ __launch_bounds__(128) void post_kernel(const float* __restrict__ in,
                                                   const float* __restrict__ Wo,
                                                   const float* __restrict__ bo,
                                                   const float* __restrict__ ln1w,
                                                   const float* __restrict__ ln1b,
                                                   const float* __restrict__ W1,
                                                   const float* __restrict__ b1,
                                                   const float* __restrict__ W2,
                                                   const float* __restrict__ b2,
                                                   const float* __restrict__ ln2w,
                                                   const float* __restrict__ ln2b,
                                                   float* __restrict__ h)
{
    const int row0 = blockIdx.x << 3;
    const int tid = threadIdx.x;
    __shared__ __align__(16) float sv[8 * DM];
    __shared__ __align__(16) float s1[8 * DM];
#pragma unroll
    for (int r = 0; r < 8; r++) sv[r * DM + tid] = in[(size_t)(row0 + r) * DM + tid];
    __syncthreads();

    float acc[8];
    {
        float bv = bo[tid];
#pragma unroll
        for (int r = 0; r < 8; r++) acc[r] = bv;
        const float4* sv4 = (const float4*)sv;
        const float4* W4 = (const float4*)Wo;
        for (int j4 = 0; j4 < 32; j4++) {
            float4 wv = W4[(size_t)tid * 32 + j4];
#pragma unroll
            for (int r = 0; r < 8; r++) {
                float4 xv = sv4[r * 32 + j4];
                acc[r] = fmaf(wv.x, xv.x, acc[r]);
                acc[r] = fmaf(wv.y, xv.y, acc[r]);
                acc[r] = fmaf(wv.z, xv.z, acc[r]);
                acc[r] = fmaf(wv.w, xv.w, acc[r]);
            }
        }
    }
    float v[8];
#pragma unroll
    for (int r = 0; r < 8; r++) v[r] = h[(size_t)(row0 + r) * DM + tid] + acc[r];
    ln_to_smem(v, ln1w, ln1b, sv, tid);
    __syncthreads();
    {
        float bv = b1[tid];
#pragma unroll
        for (int r = 0; r < 8; r++) acc[r] = bv;
        const float4* sv4 = (const float4*)sv;
        const float4* W4 = (const float4*)W1;
        for (int j4 = 0; j4 < 32; j4++) {
            float4 wv = W4[(size_t)tid * 32 + j4];
#pragma unroll
            for (int r = 0; r < 8; r++) {
                float4 xv = sv4[r * 32 + j4];
                acc[r] = fmaf(wv.x, xv.x, acc[r]);
                acc[r] = fmaf(wv.y, xv.y, acc[r]);
                acc[r] = fmaf(wv.z, xv.z, acc[r]);
                acc[r] = fmaf(wv.w, xv.w, acc[r]);
            }
        }
    }
#pragma unroll
    for (int r = 0; r < 8; r++) s1[r * DM + tid] = fmaxf(acc[r], 0.f);
    __syncthreads();
    {
        float bv = b2[tid];
#pragma unroll
        for (int r = 0; r < 8; r++) acc[r] = bv;
        const float4* s14 = (const float4*)s1;
        const float4* W4 = (const float4*)W2;
        for (int j4 = 0; j4 < 32; j4++) {
            float4 wv = W4[(size_t)tid * 32 + j4];
#pragma unroll
            for (int r = 0; r < 8; r++) {
                float4 xv = s14[r * 32 + j4];
                acc[r] = fmaf(wv.x, xv.x, acc[r]);
                acc[r] = fmaf(wv.y, xv.y, acc[r]);
                acc[r] = fmaf(wv.z, xv.z, acc[r]);
                acc[r] = fmaf(wv.w, xv.w, acc[r]);
            }
        }
    }
#pragma unroll
    for (int r = 0; r < 8; r++) v[r] = sv[r * DM + tid] + acc[r];
    ln_to_gmem(v, ln2w, ln2b, h, row0, tid);
}

// ---------------- attention scores + top-16 ---------------------------------
__global__ __launch_bounds__(128) void topk_kernel(const float* __restrict__ attn_w,
                                                   const float* __restrict__ attn_b)
{
    const int b = blockIdx.x, tid = threadIdx.x;
    __shared__ float sv[128];
    __shared__ float rv[128];
    __shared__ int ri[128];
    const float4* hp = (const float4*)(g_h + (size_t)(b * NF + tid) * DM);
    const float4* wp = (const float4*)attn_w;
    float s = attn_b[0];
#pragma unroll
    for (int i = 0; i < 32; i++) {
        float4 h4 = hp[i], w4 = wp[i];
        s = fmaf(h4.x, w4.x, s); s = fmaf(h4.y, w4.y, s);
        s = fmaf(h4.z, w4.z, s); s = fmaf(h4.w, w4.w, s);
    }
    sv[tid] = s;
    __syncthreads();
    for (int r = 0; r < 16; r++) {
        rv[tid] = sv[tid]; ri[tid] = tid;
        __syncthreads();
        for (int off = 64; off; off >>= 1) {
            if (tid < off) {
                float v2 = rv[tid + off]; int i2 = ri[tid + off];
                if (v2 > rv[tid] || (v2 == rv[tid] && i2 < ri[tid])) { rv[tid] = v2; ri[tid] = i2; }
            }
            __syncthreads();
        }
        if (tid == 0) {
            g_topidx[b * 16 + r] = ri[0];
            g_topval[b * 16 + r] = rv[0];
            sv[ri[0]] = -FLT_MAX;
        }
        __syncthreads();
    }
}

// ---------------- head: amp, pos/atom argmax, scatter -----------------------
__global__ __launch_bounds__(128) void scatter_kernel(const float* __restrict__ amp_w,
                                                      const float* __restrict__ amp_b,
                                                      const float* __restrict__ pos_w,
                                                      const float* __restrict__ pos_b,
                                                      const float* __restrict__ atom_w,
                                                      const float* __restrict__ atom_b,
                                                      const float* __restrict__ dmat,
                                                      float* __restrict__ out)
{
    const int rk = blockIdx.x, b = blockIdx.y, tid = threadIdx.x;
    __shared__ __align__(16) float vec[128];
    __shared__ float rv[128];
    __shared__ int ri[128];
    __shared__ float amp_s;
    __shared__ int jstar_s, astar_s;

    int id = g_topidx[b * 16 + rk];
    float val = g_topval[b * 16 + rk];
    vec[tid] = g_h[(size_t)(b * NF + id) * DM + tid] * val;
    __syncthreads();

    rv[tid] = vec[tid] * amp_w[tid];
    __syncthreads();
    for (int off = 64; off; off >>= 1) {
        if (tid < off) rv[tid] += rv[tid + off];
        __syncthreads();
    }
    if (tid == 0) amp_s = fmaxf(rv[0] + amp_b[0], 0.f);
    __syncthreads();

    const float4* vp = (const float4*)vec;

    float bv = -FLT_MAX; int bi = 1 << 30;
#pragma unroll
    for (int q = 0; q < 4; q++) {
        int o = q * 128 + tid;
        const float4* wp = (const float4*)(pos_w + (size_t)o * DM);
        float lg = pos_b[o];
#pragma unroll
        for (int i = 0; i < 32; i++) {
            float4 w4 = wp[i], v4 = vp[i];
            lg = fmaf(w4.x, v4.x, lg); lg = fmaf(w4.y, v4.y, lg);
            lg = fmaf(w4.z, v4.z, lg); lg = fmaf(w4.w, v4.w, lg);
        }
        if (lg > bv || (lg == bv && o < bi)) { bv = lg; bi = o; }
    }
    rv[tid] = bv; ri[tid] = bi;
    __syncthreads();
    for (int off = 64; off; off >>= 1) {
        if (tid < off) {
            float v2 = rv[tid + off]; int i2 = ri[tid + off];
            if (v2 > rv[tid] || (v2 == rv[tid] && i2 < ri[tid])) { rv[tid] = v2; ri[tid] = i2; }
        }
        __syncthreads();
    }
    if (tid == 0) jstar_s = ri[0];
    __syncthreads();

    bv = -FLT_MAX; bi = 1 << 30;
#pragma unroll
    for (int q = 0; q < 2; q++) {
        int o = q * 128 + tid;
        const float4* wp = (const float4*)(atom_w + (size_t)o * DM);
        float lg = atom_b[o];
#pragma unroll
        for (int i = 0; i < 32; i++) {
            float4 w4 = wp[i], v4 = vp[i];
            lg = fmaf(w4.x, v4.x, lg); lg = fmaf(w4.y, v4.y, lg);
            lg = fmaf(w4.z, v4.z, lg); lg = fmaf(w4.w, v4.w, lg);
        }
        if (lg > bv || (lg == bv && o < bi)) { bv = lg; bi = o; }
    }
    rv[tid] = bv; ri[tid] = bi;
    __syncthreads();
    for (int off = 64; off; off >>= 1) {
        if (tid < off) {
            float v2 = rv[tid + off]; int i2 = ri[tid + off];
            if (v2 > rv[tid] || (v2 == rv[tid] && i2 < ri[tid])) { rv[tid] = v2; ri[tid] = i2; }
        }
        __syncthreads();
    }
    if (tid == 0) astar_s = ri[0];
    __syncthreads();

    float amp = amp_s;
    int p = jstar_s * 64;
    int a = astar_s;
    for (int i = tid; i < 256; i += 128) {
        int t = p + i;
        if (t < NS)
            atomicAdd(out + (size_t)b * NS + t, dmat[(size_t)a * 256 + i] * amp);
    }
}

// ---------------------------------------------------------------------------
extern "C" void kernel_launch(void* const* d_in, const int* in_sizes, int n_in,
                              void* d_out, int out_size)
{
    const float* x         = (const float*)d_in[0];
    const float* fb        = (const float*)d_in[1];
    const float* embed_w   = (const float*)d_in[2];
    const float* embed_b   = (const float*)d_in[3];
    const float* in_proj_w = (const float*)d_in[4];
    const float* in_proj_b = (const float*)d_in[5];
    const float* out_w     = (const float*)d_in[6];
    const float* out_b     = (const float*)d_in[7];
    const float* lin1_w    = (const float*)d_in[8];
    const float* lin1_b    = (const float*)d_in[9];
    const float* lin2_w    = (const float*)d_in[10];
    const float* lin2_b    = (const float*)d_in[11];
    const float* ln1_w     = (const float*)d_in[12];
    const float* ln1_b     = (const float*)d_in[13];
    const float* ln2_w     = (const float*)d_in[14];
    const float* ln2_b     = (const float*)d_in[15];
    const float* attn_w    = (const float*)d_in[16];
    const float* attn_b    = (const float*)d_in[17];
    const float* amp_w     = (const float*)d_in[18];
    const float* amp_b     = (const float*)d_in[19];
    const float* pos_w     = (const float*)d_in[20];
    const float* pos_b     = (const float*)d_in[21];
    const float* atom_w    = (const float*)d_in[22];
    const float* atom_b    = (const float*)d_in[23];
    const float* dmat      = (const float*)d_in[24];
    float* out = (float*)d_out;

    float *p_h, *p_qkv, *p_attno;
    cudaGetSymbolAddress((void**)&p_h, g_h);
    cudaGetSymbolAddress((void**)&p_qkv, g_qkv);
    cudaGetSymbolAddress((void**)&p_attno, g_attno);

    twid_kernel<<<2, 256>>>();
    ewt_kernel<<<(161 * 128 + 255) / 256, 256>>>(embed_w);
    filt_kernel<<<64, 256>>>(fb);
    conv_fft_kernel<<<dim3(64, NB), 256>>>(x);

    embed_kernel<<<NB * NF / 8, 128>>>(embed_b);

    for (int i = 0; i < 6; i++) {
        qkv_kernel<<<512, 128>>>(p_h, in_proj_w + (size_t)i * 384 * 128,
                                 in_proj_b + i * 384, p_qkv);
        attn_kernel<<<dim3(4, NB), 128>>>();
        post_kernel<<<512, 128>>>(p_attno,
                                  out_w + (size_t)i * 128 * 128, out_b + i * 128,
                                  ln1_w + i * 128, ln1_b + i * 128,
                                  lin1_w + (size_t)i * 128 * 128, lin1_b + i * 128,
                                  lin2_w + (size_t)i * 128 * 128, lin2_b + i * 128,
                                  ln2_w + i * 128, ln2_b + i * 128, p_h);
    }

    topk_kernel<<<NB, 128>>>(attn_w, attn_b);
    cudaMemsetAsync(d_out, 0, (size_t)out_size * sizeof(float), 0);
    scatter_kernel<<<dim3(16, NB), 128>>>(amp_w, amp_b, pos_w, pos_b,
                                          atom_w, atom_b, dmat, out);
}

// round 14
// speedup vs baseline: 1.1210x; 1.0082x over previous
#include <cuda_runtime.h>
#include <math.h>
#include <float.h>

#define NB 32
#define NS 32768
#define NF 128
#define DM 128

// ------------------------- scratch (device globals) -------------------------
__device__ float2 g_twid[512];            // exp(-2*pi*i*k/1024)
__device__ float2 g_P[64 * 1024];         // conj(FFT(w_2c - i w_2c+1)), scrambled
__device__ float g_ewT[161 * 128];        // transposed embed weights
__device__ float g_chunk[NB * NF * DM];
__device__ float g_h[NB * NF * DM];
__device__ float g_qkv[NB * NF * 384];
__device__ float g_attno[NB * NF * DM];
__device__ int   g_topidx[NB * 16];
__device__ float g_topval[NB * 16];

// ------------------------- butterflies ---------------------------------------
__device__ __forceinline__ void bf_dif(float& ar, float& ai, float& br, float& bi, float2 w)
{
    float xr = ar - br, xi = ai - bi;
    ar += br; ai += bi;
    br = xr * w.x - xi * w.y;
    bi = xr * w.y + xi * w.x;
}
__device__ __forceinline__ void bf_dit(float& ar, float& ai, float& br, float& bi, float2 w)
{
    float tr = br * w.x + bi * w.y;
    float ti = bi * w.x - br * w.y;
    br = ar - tr; bi = ai - ti;
    ar += tr; ai += ti;
}

// ------------------------- forward 1024-pt DIF (in-place, natural->bitrev) ---
__device__ __forceinline__ void fft1024_dif(float* re, float* im, const float2* tw, int tid)
{
    {   // stages h=512, 256
        int r = tid;
        float ar = re[r],       ai = im[r];
        float br = re[r + 256], bi = im[r + 256];
        float cr = re[r + 512], ci = im[r + 512];
        float dr = re[r + 768], di = im[r + 768];
        bf_dif(ar, ai, cr, ci, tw[r]);
        bf_dif(br, bi, dr, di, tw[r + 256]);
        float2 v = tw[2 * r];
        bf_dif(ar, ai, br, bi, v);
        bf_dif(cr, ci, dr, di, v);
        re[r] = ar;       im[r] = ai;
        re[r + 256] = br; im[r + 256] = bi;
        re[r + 512] = cr; im[r + 512] = ci;
        re[r + 768] = dr; im[r + 768] = di;
    }
    __syncthreads();
    {   // stages h=128, 64
        int q = tid >> 6, r = tid & 63, i0 = q * 256 + r;
        float ar = re[i0],       ai = im[i0];
        float br = re[i0 + 64],  bi = im[i0 + 64];
        float cr = re[i0 + 128], ci = im[i0 + 128];
        float dr = re[i0 + 192], di = im[i0 + 192];
        bf_dif(ar, ai, cr, ci, tw[4 * r]);
        bf_dif(br, bi, dr, di, tw[4 * r + 256]);
        float2 v = tw[8 * r];
        bf_dif(ar, ai, br, bi, v);
        bf_dif(cr, ci, dr, di, v);
        re[i0] = ar;       im[i0] = ai;
        re[i0 + 64] = br;  im[i0 + 64] = bi;
        re[i0 + 128] = cr; im[i0 + 128] = ci;
        re[i0 + 192] = dr; im[i0 + 192] = di;
    }
    __syncthreads();
    {   // stages h=32..4 (shuffle), 2,1 (in-thread)
        float4 R = ((const float4*)re)[tid];
        float4 I = ((const float4*)im)[tid];
        float vr[4] = {R.x, R.y, R.z, R.w};
        float vi[4] = {I.x, I.y, I.z, I.w};
#pragma unroll
        for (int s = 3; s >= 0; s--) {
            const int mask = 1 << s;
            const int step = 128 >> s;
            const int kb = 4 * (tid & (mask - 1));
            const bool up = (tid & mask) != 0;
#pragma unroll
            for (int j = 0; j < 4; j++) {
                float orr = __shfl_xor_sync(0xffffffffu, vr[j], mask);
                float oii = __shfl_xor_sync(0xffffffffu, vi[j], mask);
                float2 w = tw[(kb + j) * step];
                float sr = vr[j] + orr, si = vi[j] + oii;
                float dr = orr - vr[j], di = oii - vi[j];
                float pr = dr * w.x - di * w.y;
                float pi = dr * w.y + di * w.x;
                vr[j] = up ? pr : sr;
                vi[j] = up ? pi : si;
            }
        }
        {
            float s0r = vr[0] + vr[2], s0i = vi[0] + vi[2];
            float d0r = vr[0] - vr[2], d0i = vi[0] - vi[2];
            vr[0] = s0r; vi[0] = s0i; vr[2] = d0r; vi[2] = d0i;
            float s1r = vr[1] + vr[3], s1i = vi[1] + vi[3];
            float d1r = vr[1] - vr[3], d1i = vi[1] - vi[3];
            vr[1] = s1r; vi[1] = s1i;
            vr[3] = d1i; vi[3] = -d1r;
        }
        {
            float t0r = vr[0] + vr[1], t0i = vi[0] + vi[1];
            float t1r = vr[0] - vr[1], t1i = vi[0] - vi[1];
            float t2r = vr[2] + vr[3], t2i = vi[2] + vi[3];
            float t3r = vr[2] - vr[3], t3i = vi[2] - vi[3];
            vr[0] = t0r; vi[0] = t0i; vr[1] = t1r; vi[1] = t1i;
            vr[2] = t2r; vi[2] = t2i; vr[3] = t3r; vi[3] = t3i;
        }
        ((float4*)re)[tid] = make_float4(vr[0], vr[1], vr[2], vr[3]);
        ((float4*)im)[tid] = make_float4(vi[0], vi[1], vi[2], vi[3]);
    }
    __syncthreads();
}

// ------------------------- precompute kernels --------------------------------
__global__ void twid_kernel()
{
    int k = blockIdx.x * 256 + threadIdx.x;
    if (k < 512) {
        double a = -2.0 * 3.14159265358979323846 * (double)k / 1024.0;
        g_twid[k] = make_float2((float)cos(a), (float)sin(a));
    }
}

__global__ __launch_bounds__(256) void filt_kernel(const float* __restrict__ fb)
{
    __shared__ __align__(16) float re[1024], im[1024];
    __shared__ __align__(16) float2 tw[512];
    const int c = blockIdx.x, tid = threadIdx.x;
    tw[tid] = g_twid[tid]; tw[tid + 256] = g_twid[tid + 256];
    for (int i = tid; i < 1024; i += 256) {
        re[i] = (i < 512) ? fb[(size_t)(2 * c) * 512 + i] : 0.f;
        im[i] = (i < 512) ? -fb[(size_t)(2 * c + 1) * 512 + i] : 0.f;
    }
    __syncthreads();
    fft1024_dif(re, im, tw, tid);
    for (int i = tid; i < 1024; i += 256)
        g_P[(size_t)c * 1024 + i] = make_float2(re[i], -im[i]);
}

__global__ void ewt_kernel(const float* __restrict__ ew)
{
    int i = blockIdx.x * 256 + threadIdx.x;
    if (i < 161 * 128) {
        int j = i >> 7, c = i & 127;
        g_ewT[j * 128 + c] = ew[(size_t)c * 161 + j];
    }
}

// ---- trip A: fused pointwise(U*P) + DIT stages 1..64; result to z slot -------
__device__ __forceinline__ void ifft_stageA(const float ur[4], const float ui[4],
                                            const float4* __restrict__ Pp,
                                            const float2* twA, int tid,
                                            float* zr, float* zi)
{
    float4 P0 = Pp[2 * tid], P1 = Pp[2 * tid + 1];
    float vr[4], vi[4];
    vr[0] = ur[0] * P0.x - ui[0] * P0.y; vi[0] = ur[0] * P0.y + ui[0] * P0.x;
    vr[1] = ur[1] * P0.z - ui[1] * P0.w; vi[1] = ur[1] * P0.w + ui[1] * P0.z;
    vr[2] = ur[2] * P1.x - ui[2] * P1.y; vi[2] = ur[2] * P1.y + ui[2] * P1.x;
    vr[3] = ur[3] * P1.z - ui[3] * P1.w; vi[3] = ur[3] * P1.w + ui[3] * P1.z;
    {   // h=1 (Wc=1)
        float t0r = vr[0] + vr[1], t0i = vi[0] + vi[1];
        float t1r = vr[0] - vr[1], t1i = vi[0] - vi[1];
        float t2r = vr[2] + vr[3], t2i = vi[2] + vi[3];
        float t3r = vr[2] - vr[3], t3i = vi[2] - vi[3];
        vr[0] = t0r; vi[0] = t0i; vr[1] = t1r; vi[1] = t1i;
        vr[2] = t2r; vi[2] = t2i; vr[3] = t3r; vi[3] = t3i;
    }
    {   // h=2: (0,2) Wc=1; (1,3) Wc=(0,1)
        float s0r = vr[0] + vr[2], s0i = vi[0] + vi[2];
        float d0r = vr[0] - vr[2], d0i = vi[0] - vi[2];
        vr[0] = s0r; vi[0] = s0i; vr[2] = d0r; vi[2] = d0i;
        float tr = -vi[3], ti = vr[3];
        float nr = vr[1] + tr, ni = vi[1] + ti;
        float mr = vr[1] - tr, mi = vi[1] - ti;
        vr[1] = nr; vi[1] = ni; vr[3] = mr; vi[3] = mi;
    }
#pragma unroll
    for (int s = 0; s < 5; s++) {               // h = 4,8,16,32,64
        const int mask = 1 << s;
        const int offA = 4 * (mask - 1);
        const int ib = tid & (mask - 1);
#pragma unroll
        for (int j = 0; j < 4; j++) {
            float orr = __shfl_xor_sync(0xffffffffu, vr[j], mask);
            float oii = __shfl_xor_sync(0xffffffffu, vi[j], mask);
            float2 tww = twA[offA + (j << s) + ib];
            const bool up = (tid & mask) != 0;
            float sr = up ? vr[j] : orr;
            float sI = up ? vi[j] : oii;
            float tr = sr * tww.x + sI * tww.y;
            float ti = sI * tww.x - sr * tww.y;
            float lr = vr[j] + tr, li = vi[j] + ti;
            float ur_ = orr - tr, ui_ = oii - ti;
            vr[j] = up ? ur_ : lr;
            vi[j] = up ? ui_ : li;
        }
    }
    ((float4*)zr)[tid] = make_float4(vr[0], vr[1], vr[2], vr[3]);
    ((float4*)zi)[tid] = make_float4(vi[0], vi[1], vi[2], vi[3]);
}

// ------------------------- FFT conv + |.| + pool -----------------------------
__global__ __launch_bounds__(256) void conv_fft_kernel(const float* __restrict__ x)
{
    __shared__ __align__(16) float uRe[1024], uIm[1024];
    __shared__ __align__(16) float zRe[2048], zIm[2048];
    __shared__ __align__(16) float2 tw[512];
    __shared__ __align__(16) float2 twA[124];
    __shared__ float cs0[128], cs1[128];
    __shared__ float wpart[2][4][4];
    const int seg = blockIdx.x, b = blockIdx.y;
    const int tid = threadIdx.x, w = tid >> 5, lane = tid & 31;

    tw[tid] = g_twid[tid]; tw[tid + 256] = g_twid[tid + 256];
    if (tid < 124) {
        int e = tid, s, base0;
        if (e < 4)       { s = 0; base0 = 0; }
        else if (e < 12) { s = 1; base0 = 4; }
        else if (e < 28) { s = 2; base0 = 12; }
        else if (e < 60) { s = 3; base0 = 28; }
        else             { s = 4; base0 = 60; }
        int r = e - base0;
        int j = r >> s;
        int i = r & ((1 << s) - 1);
        twA[e] = g_twid[(4 * i + j) * (128 >> s)];
    }
    const float* xb = x + (size_t)b * NS;
    const int base = seg * 512 - 256;
    for (int i = tid; i < 1024; i += 256) {
        int g = base + i;
        uRe[i] = (g >= 0 && g < NS) ? xb[g] : 0.f;
        uIm[i] = 0.f;
    }
    if (tid < 128) { cs0[tid] = 0.f; cs1[tid] = 0.f; }
    __syncthreads();
    fft1024_dif(uRe, uIm, tw, tid);

    float ur[4], ui[4];
    {
        float4 R = ((const float4*)uRe)[tid];
        float4 I = ((const float4*)uIm)[tid];
        ur[0] = R.x; ur[1] = R.y; ur[2] = R.z; ur[3] = R.w;
        ui[0] = I.x; ui[1] = I.y; ui[2] = I.z; ui[3] = I.w;
    }
    const int rB = tid & 127;
    const float2 t4r  = tw[4 * rB];
    const float2 t2r  = tw[2 * rB];
    const float2 t2r2 = tw[2 * rB + 256];
    const float2 t5a = tw[rB], t5b = tw[rB + 128], t5c = tw[rB + 256], t5d = tw[rB + 384];

    for (int p = 0; p < 64; p += 2) {
        ifft_stageA(ur, ui, (const float4*)(g_P + (size_t)p * 1024), twA, tid, zRe, zIm);
        ifft_stageA(ur, ui, (const float4*)(g_P + (size_t)(p + 1) * 1024), twA, tid,
                    zRe + 1024, zIm + 1024);
        __syncthreads();

        const int s = tid >> 7;
        const float* zr = zRe + (s << 10);
        const float* zi = zIm + (s << 10);
        float xr[8], xi[8];
#pragma unroll
        for (int k = 0; k < 8; k++) { xr[k] = zr[rB + (k << 7)]; xi[k] = zi[rB + (k << 7)]; }
        bf_dit(xr[0], xi[0], xr[1], xi[1], t4r);
        bf_dit(xr[2], xi[2], xr[3], xi[3], t4r);
        bf_dit(xr[4], xi[4], xr[5], xi[5], t4r);
        bf_dit(xr[6], xi[6], xr[7], xi[7], t4r);
        bf_dit(xr[0], xi[0], xr[2], xi[2], t2r);
        bf_dit(xr[1], xi[1], xr[3], xi[3], t2r2);
        bf_dit(xr[4], xi[4], xr[6], xi[6], t2r);
        bf_dit(xr[5], xi[5], xr[7], xi[7], t2r2);
        {
            float tr, ti;
            tr = xr[4] * t5a.x + xi[4] * t5a.y; ti = xi[4] * t5a.x - xr[4] * t5a.y;
            xr[0] += tr; xi[0] += ti;
            tr = xr[5] * t5b.x + xi[5] * t5b.y; ti = xi[5] * t5b.x - xr[5] * t5b.y;
            xr[1] += tr; xi[1] += ti;
            tr = xr[6] * t5c.x + xi[6] * t5c.y; ti = xi[6] * t5c.x - xr[6] * t5c.y;
            xr[2] += tr; xi[2] += ti;
            tr = xr[7] * t5d.x + xi[7] * t5d.y; ti = xi[7] * t5d.x - xr[7] * t5d.y;
            xr[3] += tr; xi[3] += ti;
        }
        float v0 = fabsf(xr[0]) + fabsf(xr[1]);
        float v1 = fabsf(xi[0]) + fabsf(xi[1]);
        float v2 = fabsf(xr[2]) + fabsf(xr[3]);
        float v3 = fabsf(xi[2]) + fabsf(xi[3]);
#pragma unroll
        for (int o = 16; o; o >>= 1) {
            v0 += __shfl_xor_sync(0xffffffffu, v0, o);
            v1 += __shfl_xor_sync(0xffffffffu, v1, o);
            v2 += __shfl_xor_sync(0xffffffffu, v2, o);
            v3 += __shfl_xor_sync(0xffffffffu, v3, o);
        }
        if (lane == 0) {
            wpart[s][w & 3][0] = v0; wpart[s][w & 3][1] = v1;
            wpart[s][w & 3][2] = v2; wpart[s][w & 3][3] = v3;
        }
        __syncthreads();
        if (tid < 8) {
            int pr = tid >> 2, q = tid & 3;
            float sm = wpart[pr][0][q] + wpart[pr][1][q] + wpart[pr][2][q] + wpart[pr][3][q];
            int pp = p + pr;
            if (q == 0)      cs0[2 * pp]     += sm;
            else if (q == 1) cs0[2 * pp + 1] += sm;
            else if (q == 2) cs1[2 * pp]     += sm;
            else             cs1[2 * pp + 1] += sm;
        }
        __syncthreads();
    }
    const float scale = 1.f / (1024.f * 512.f);
    if (tid < 128) {
        g_chunk[((size_t)b * NF + 2 * seg) * DM + tid]     = cs0[tid] * scale;
        g_chunk[((size_t)b * NF + 2 * seg + 1) * DM + tid] = cs1[tid] * scale;
    }
}

// ---------------- frames + pos-encoding + embed (8 rows / block) -------------
__global__ __launch_bounds__(128) void embed_kernel(const float* __restrict__ eb)
{
    const int row0 = blockIdx.x << 3;
    const int tid = threadIdx.x;
    __shared__ float vec[8][161];
    for (int idx = tid; idx < 1024; idx += 128) {
        int r = idx >> 7, ch = idx & 127;
        int row = row0 + r, t = row & 127;
        float f = g_chunk[(size_t)row * DM + ch];
        if (t > 0) f += g_chunk[(size_t)(row - 1) * DM + ch];
        vec[r][ch] = f;
    }
    for (int idx = tid; idx < 264; idx += 128) {
        int r = idx / 33, kk = idx % 33;
        int t = (row0 + r) & 127;
        float pos = (t == 127) ? 1.0f
                               : __fadd_rn(-1.0f, __fmul_rn((float)t, __fdiv_rn(2.0f, 127.0f)));
        float v;
        if (kk == 0) v = pos;
        else {
            int k = (kk <= 16) ? (kk - 1) : (kk - 17);
            float fr = __fmul_rn(exp2f((float)k), 3.14159274101257324f);
            float prod = __fmul_rn(pos, fr);
            v = (kk <= 16) ? (float)sin((double)prod) : (float)cos((double)prod);
        }
        vec[r][128 + kk] = v;
    }
    __syncthreads();
    float acc[8];
    float bv = eb[tid];
#pragma unroll
    for (int r = 0; r < 8; r++) acc[r] = bv;
    for (int j = 0; j < 161; j++) {
        float wv = g_ewT[j * 128 + tid];
#pragma unroll
        for (int r = 0; r < 8; r++) acc[r] = fmaf(vec[r][j], wv, acc[r]);
    }
#pragma unroll
    for (int r = 0; r < 8; r++)
        g_h[(size_t)(row0 + r) * DM + tid] = acc[r];
}

// ---------------- qkv linear (K = 128, NO = 3) -------------------------------
__global__ __launch_bounds__(128) void qkv_kernel(const float* __restrict__ in,
                                                  const float* __restrict__ W,
                                                  const float* __restrict__ bias,
                                                  float* __restrict__ out)
{
    const int row0 = blockIdx.x << 3;
    const int tid = threadIdx.x;
    __shared__ __align__(16) float sv[8 * DM];
#pragma unroll
    for (int r = 0; r < 8; r++) sv[r * DM + tid] = in[(size_t)(row0 + r) * DM + tid];
    __syncthreads();
    float acc[3][8];
#pragma unroll
    for (int o = 0; o < 3; o++) {
        float bv = bias[o * DM + tid];
#pragma unroll
        for (int r = 0; r < 8; r++) acc[o][r] = bv;
    }
    const float4* sv4 = (const float4*)sv;
    const float4* W4 = (const float4*)W;
    for (int j4 = 0; j4 < 32; j4++) {
        float4 wv[3];
#pragma unroll
        for (int o = 0; o < 3; o++) wv[o] = W4[(size_t)(o * DM + tid) * 32 + j4];
#pragma unroll
        for (int r = 0; r < 8; r++) {
            float4 xv = sv4[r * 32 + j4];
#pragma unroll
            for (int o = 0; o < 3; o++) {
                acc[o][r] = fmaf(wv[o].x, xv.x, acc[o][r]);
                acc[o][r] = fmaf(wv[o].y, xv.y, acc[o][r]);
                acc[o][r] = fmaf(wv[o].z, xv.z, acc[o][r]);
                acc[o][r] = fmaf(wv[o].w, xv.w, acc[o][r]);
            }
        }
    }
#pragma unroll
    for (int r = 0; r < 8; r++)
#pragma unroll
        for (int o = 0; o < 3; o++)
            out[(size_t)(row0 + r) * 384 + o * DM + tid] = acc[o][r];
}

// ---------------- attention: split-K, one CTA per (head, batch) --------------
// smem 33KB: merge partials alias ks (32x128 floats); m/l alias vs.
__global__ __launch_bounds__(256) void attn_kernel()
{
    const int hd = blockIdx.x, b = blockIdx.y;
    const int tid = threadIdx.x;
    const int half = tid >> 7, qi = tid & 127;
    __shared__ __align__(16) float ks[NF * 32];
    __shared__ __align__(16) float vs[NF * 32];
    const float* base = g_qkv + (size_t)b * NF * 384;

    for (int idx = tid; idx < NF * 32; idx += 256) {
        int j = idx >> 5, i = idx & 31;
        ks[idx] = base[j * 384 + 128 + hd * 32 + i];
        vs[idx] = base[j * 384 + 256 + hd * 32 + i];
    }
    float q[32];
    {
        const float4* qp = (const float4*)(base + (size_t)qi * 384 + hd * 32);
#pragma unroll
        for (int i = 0; i < 8; i++) {
            float4 v = qp[i];
            q[4 * i] = v.x; q[4 * i + 1] = v.y; q[4 * i + 2] = v.z; q[4 * i + 3] = v.w;
        }
    }
    __syncthreads();

    float o[32];
#pragma unroll
    for (int i = 0; i < 32; i++) o[i] = 0.f;
    float m = -FLT_MAX, l = 0.f;
    const float scale = 0.17677669529663689f;
    const int j0 = half << 6;

    for (int j = j0; j < j0 + 64; j += 2) {
        const float4* kp1 = (const float4*)(ks + j * 32);
        const float4* kp2 = (const float4*)(ks + j * 32 + 32);
        float s1 = 0.f, s2 = 0.f;
#pragma unroll
        for (int i = 0; i < 8; i++) {
            float4 k1 = kp1[i], k2 = kp2[i];
            s1 = fmaf(q[4 * i], k1.x, s1); s2 = fmaf(q[4 * i], k2.x, s2);
            s1 = fmaf(q[4 * i + 1], k1.y, s1); s2 = fmaf(q[4 * i + 1], k2.y, s2);
            s1 = fmaf(q[4 * i + 2], k1.z, s1); s2 = fmaf(q[4 * i + 2], k2.z, s2);
            s1 = fmaf(q[4 * i + 3], k1.w, s1); s2 = fmaf(q[4 * i + 3], k2.w, s2);
        }
        s1 *= scale; s2 *= scale;
        float mn = fmaxf(m, fmaxf(s1, s2));
        float c = expf(m - mn);
        float p1 = expf(s1 - mn);
        float p2 = expf(s2 - mn);
        l = l * c + p1 + p2;
        const float4* vp1 = (const float4*)(vs + j * 32);
        const float4* vp2 = (const float4*)(vs + j * 32 + 32);
#pragma unroll
        for (int i = 0; i < 8; i++) {
            float4 v1 = vp1[i], v2 = vp2[i];
            o[4 * i]     = fmaf(p2, v2.x, fmaf(p1, v1.x, o[4 * i] * c));
            o[4 * i + 1] = fmaf(p2, v2.y, fmaf(p1, v1.y, o[4 * i + 1] * c));
            o[4 * i + 2] = fmaf(p2, v2.z, fmaf(p1, v1.z, o[4 * i + 2] * c));
            o[4 * i + 3] = fmaf(p2, v2.w, fmaf(p1, v1.w, o[4 * i + 3] * c));
        }
        m = mn;
    }
    // both halves done reading ks/vs -> reuse them as the merge buffer
    __syncthreads();
    if (half == 1) {
        vs[qi] = m; vs[128 + qi] = l;
#pragma unroll
        for (int i = 0; i < 32; i++) ks[i * 128 + qi] = o[i];
    }
    __syncthreads();
    if (half == 0) {
        float m2 = vs[qi], l2 = vs[128 + qi];
        float mn = fmaxf(m, m2);
        float c1 = expf(m - mn), c2 = expf(m2 - mn);
        float inv = 1.f / (l * c1 + l2 * c2);
        float* dst = g_attno + (size_t)(b * NF + qi) * DM + hd * 32;
#pragma unroll
        for (int i = 0; i < 32; i++)
            dst[i] = (o[i] * c1 + ks[i * 128 + qi] * c2) * inv;
    }
}

// ---------------- LN epilogues ------------------------------------------------
__device__ __forceinline__ void ln_to_gmem(float v[8], const float* lnw, const float* lnb,
                                           float* h, int row0, int tid)
{
    __shared__ float red[4][8];
    const int w = tid >> 5;
    float mean[8];
#pragma unroll
    for (int r = 0; r < 8; r++) {
        float s = v[r];
#pragma unroll
        for (int o = 16; o; o >>= 1) s += __shfl_xor_sync(0xffffffffu, s, o);
        if ((tid & 31) == 0) red[w][r] = s;
    }
    __syncthreads();
#pragma unroll
    for (int r = 0; r < 8; r++)
        mean[r] = (red[0][r] + red[1][r] + red[2][r] + red[3][r]) * 0.0078125f;
    __syncthreads();
#pragma unroll
    for (int r = 0; r < 8; r++) {
        float dv = v[r] - mean[r];
        float s = dv * dv;
#pragma unroll
        for (int o = 16; o; o >>= 1) s += __shfl_xor_sync(0xffffffffu, s, o);
        if ((tid & 31) == 0) red[w][r] = s;
        v[r] = dv;
    }
    __syncthreads();
    float lw = lnw[tid], lb = lnb[tid];
#pragma unroll
    for (int r = 0; r < 8; r++) {
        float var = (red[0][r] + red[1][r] + red[2][r] + red[3][r]) * 0.0078125f;
        h[(size_t)(row0 + r) * DM + tid] = v[r] * (1.f / sqrtf(var + 1e-5f)) * lw + lb;
    }
}

__device__ __forceinline__ void ln_to_smem(float v[8], const float* lnw, const float* lnb,
                                           float* dst, int tid)
{
    __shared__ float red2[4][8];
    const int w = tid >> 5;
    float mean[8];
#pragma unroll
    for (int r = 0; r < 8; r++) {
        float s = v[r];
#pragma unroll
        for (int o = 16; o; o >>= 1) s += __shfl_xor_sync(0xffffffffu, s, o);
        if ((tid & 31) == 0) red2[w][r] = s;
    }
    __syncthreads();
#pragma unroll
    for (int r = 0; r < 8; r++)
        mean[r] = (red2[0][r] + red2[1][r] + red2[2][r] + red2[3][r]) * 0.0078125f;
    __syncthreads();
#pragma unroll
    for (int r = 0; r < 8; r++) {
        float dv = v[r] - mean[r];
        float s = dv * dv;
#pragma unroll
        for (int o = 16; o; o >>= 1) s += __shfl_xor_sync(0xffffffffu, s, o);
        if ((tid & 31) == 0) red2[w][r] = s;
        v[r] = dv;
    }
    __syncthreads();
    float lw = lnw[tid], lb = lnb[tid];
#pragma unroll
    for (int r = 0; r < 8; r++) {
        float var = (red2[0][r] + red2[1][r] + red2[2][r] + red2[3][r]) * 0.0078125f;
        dst[r * DM + tid] = v[r] * (1.f / sqrtf(var + 1e-5f)) * lw + lb;
    }
}

// LN writing BOTH gmem h and smem dst (for fused next-layer qkv)
__device__ __forceinline__ void ln_to_both(float v[8], const float* lnw, const float* lnb,
                                           float* h, int row0, float* dst, int tid)
{
    __shared__ float red3[4][8];
    const int w = tid >> 5;
    float mean[8];
#pragma unroll
    for (int r = 0; r < 8; r++) {
        float s = v[r];
#pragma unroll
        for (int o = 16; o; o >>= 1) s += __shfl_xor_sync(0xffffffffu, s, o);
        if ((tid & 31) == 0) red3[w][r] = s;
    }
    __syncthreads();
#pragma unroll
    for (int r = 0; r < 8; r++)
        mean[r] = (red3[0][r] + red3[1][r] + red3[2][r] + red3[3][r]) * 0.0078125f;
    __syncthreads();
#pragma unroll
    for (int r = 0; r < 8; r++) {
        float dv = v[r] - mean[r];
        float s = dv * dv;
#pragma unroll
        for (int o = 16; o; o >>= 1) s += __shfl_xor_sync(0xffffffffu, s, o);
        if ((tid & 31) == 0) red3[w][r] = s;
        v[r] = dv;
    }
    __syncthreads();
    float lw = lnw[tid], lb = lnb[tid];
#pragma unroll
    for (int r = 0; r < 8; r++) {
        float var = (red3[0][r] + red3[1][r] + red3[2][r] + red3[3][r]) * 0.0078125f;
        float outv = v[r] * (1.f / sqrtf(var + 1e-5f)) * lw + lb;
        h[(size_t)(row0 + r) * DM + tid] = outv;
        dst[r * DM + tid] = outv;
    }
}

// ---------------- post: proj+res+LN1+FFN+res+LN2 (+ next-layer qkv) ----------
__global__ __launch_bounds__(128) void post_kernel(const float* __restrict__ in,
                                                   const float* __restrict__ Wo,
                                                   const float* __restrict__ bo,
                                                   const float* __restrict__ ln1w,
                                                   const float* __restrict__ ln1b,
                                                   const float* __restrict__ W1,
                                                   const float* __restrict__ b1,
                                                   const float* __restrict__ W2,
                                                   const float* __restrict__ b2,
                                                   const float* __restrict__ ln2w,
                                                   const float* __restrict__ ln2b,
                                                   float* __restrict__ h,
                                                   const float* __restrict__ Wn,
                                                   const float* __restrict__ bn,
                                                   float* __restrict__ qkv_out)
{
    const int row0 = blockIdx.x << 3;
    const int tid = threadIdx.x;
    __shared__ __align__(16) float sv[8 * DM];
    __shared__ __align__(16) float s1[8 * DM];
#pragma unroll
    for (int r = 0; r < 8; r++) sv[r * DM + tid] = in[(size_t)(row0 + r) * DM + tid];
    __syncthreads();

    float acc[8];
    {
        float bv = bo[tid];
#pragma unroll
        for (int r = 0; r < 8; r++) acc[r] = bv;
        const float4* sv4 = (const float4*)sv;
        const float4* W4 = (const float4*)Wo;
        for (int j4 = 0; j4 < 32; j4++) {
            float4 wv = W4[(size_t)tid * 32 + j4];
#pragma unroll
            for (int r = 0; r < 8; r++) {
                float4 xv = sv4[r * 32 + j4];
                acc[r] = fmaf(wv.x, xv.x, acc[r]);
                acc[r] = fmaf(wv.y, xv.y, acc[r]);
                acc[r] = fmaf(wv.z, xv.z, acc[r]);
                acc[r] = fmaf(wv.w, xv.w, acc[r]);
            }
        }
    }
    float v[8];
#pragma unroll
    for (int r = 0; r < 8; r++) v[r] = h[(size_t)(row0 + r) * DM + tid] + acc[r];
    ln_to_smem(v, ln1w, ln1b, sv, tid);
    __syncthreads();
    {
        float bv = b1[tid];
#pragma unroll
        for (int r = 0; r < 8; r++) acc[r] = bv;
        const float4* sv4 = (const float4*)sv;
        const float4* W4 = (const float4*)W1;
        for (int j4 = 0; j4 < 32; j4++) {
            float4 wv = W4[(size_t)tid * 32 + j4];
#pragma unroll
            for (int r = 0; r < 8; r++) {
                float4 xv = sv4[r * 32 + j4];
                acc[r] = fmaf(wv.x, xv.x, acc[r]);
                acc[r] = fmaf(wv.y, xv.y, acc[r]);
                acc[r] = fmaf(wv.z, xv.z, acc[r]);
                acc[r] = fmaf(wv.w, xv.w, acc[r]);
            }
        }
    }
#pragma unroll
    for (int r = 0; r < 8; r++) s1[r * DM + tid] = fmaxf(acc[r], 0.f);
    __syncthreads();
    {
        float bv = b2[tid];
#pragma unroll
        for (int r = 0; r < 8; r++) acc[r] = bv;
        const float4* s14 = (const float4*)s1;
        const float4* W4 = (const float4*)W2;
        for (int j4 = 0; j4 < 32; j4++) {
            float4 wv = W4[(size_t)tid * 32 + j4];
#pragma unroll
            for (int r = 0; r < 8; r++) {
                float4 xv = s14[r * 32 + j4];
                acc[r] = fmaf(wv.x, xv.x, acc[r]);
                acc[r] = fmaf(wv.y, xv.y, acc[r]);
                acc[r] = fmaf(wv.z, xv.z, acc[r]);
                acc[r] = fmaf(wv.w, xv.w, acc[r]);
            }
        }
    }
#pragma unroll
    for (int r = 0; r < 8; r++) v[r] = sv[r * DM + tid] + acc[r];

    if (Wn == nullptr) {
        ln_to_gmem(v, ln2w, ln2b, h, row0, tid);
        return;
    }
    ln_to_both(v, ln2w, ln2b, h, row0, sv, tid);
    __syncthreads();

    // fused next-layer qkv on the LN2 output rows (identical order to qkv_kernel)
    float accq[3][8];
#pragma unroll
    for (int o = 0; o < 3; o++) {
        float bv = bn[o * DM + tid];
#pragma unroll
        for (int r = 0; r < 8; r++) accq[o][r] = bv;
    }
    const float4* sv4 = (const float4*)sv;
    const float4* W4 = (const float4*)Wn;
    for (int j4 = 0; j4 < 32; j4++) {
        float4 wv[3];
#pragma unroll
        for (int o = 0; o < 3; o++) wv[o] = W4[(size_t)(o * DM + tid) * 32 + j4];
#pragma unroll
        for (int r = 0; r < 8; r++) {
            float4 xv = sv4[r * 32 + j4];
#pragma unroll
            for (int o = 0; o < 3; o++) {
                accq[o][r] = fmaf(wv[o].x, xv.x, accq[o][r]);
                accq[o][r] = fmaf(wv[o].y, xv.y, accq[o][r]);
                accq[o][r] = fmaf(wv[o].z, xv.z, accq[o][r]);
                accq[o][r] = fmaf(wv[o].w, xv.w, accq[o][r]);
            }
        }
    }
#pragma unroll
    for (int r = 0; r < 8; r++)
#pragma unroll
        for (int o = 0; o < 3; o++)
            qkv_out[(size_t)(row0 + r) * 384 + o * DM + tid] = accq[o][r];
}

// ---------------- attention scores + top-16 ---------------------------------
__global__ __launch_bounds__(128) void topk_kernel(const float* __restrict__ attn_w,
                                                   const float* __restrict__ attn_b)
{
    const int b = blockIdx.x, tid = threadIdx.x;
    __shared__ float sv[128];
    __shared__ float rv[128];
    __shared__ int ri[128];
    const float4* hp = (const float4*)(g_h + (size_t)(b * NF + tid) * DM);
    const float4* wp = (const float4*)attn_w;
    float s = attn_b[0];
#pragma unroll
    for (int i = 0; i < 32; i++) {
        float4 h4 = hp[i], w4 = wp[i];
        s = fmaf(h4.x, w4.x, s); s = fmaf(h4.y, w4.y, s);
        s = fmaf(h4.z, w4.z, s); s = fmaf(h4.w, w4.w, s);
    }
    sv[tid] = s;
    __syncthreads();
    for (int r = 0; r < 16; r++) {
        rv[tid] = sv[tid]; ri[tid] = tid;
        __syncthreads();
        for (int off = 64; off; off >>= 1) {
            if (tid < off) {
                float v2 = rv[tid + off]; int i2 = ri[tid + off];
                if (v2 > rv[tid] || (v2 == rv[tid] && i2 < ri[tid])) { rv[tid] = v2; ri[tid] = i2; }
            }
            __syncthreads();
        }
        if (tid == 0) {
            g_topidx[b * 16 + r] = ri[0];
            g_topval[b * 16 + r] = rv[0];
            sv[ri[0]] = -FLT_MAX;
        }
        __syncthreads();
    }
}

// ---------------- head: amp, pos/atom argmax, scatter -----------------------
__global__ __launch_bounds__(128) void scatter_kernel(const float* __restrict__ amp_w,
                                                      const float* __restrict__ amp_b,
                                                      const float* __restrict__ pos_w,
                                                      const float* __restrict__ pos_b,
                                                      const float* __restrict__ atom_w,
                                                      const float* __restrict__ atom_b,
                                                      const float* __restrict__ dmat,
                                                      float* __restrict__ out)
{
    const int rk = blockIdx.x, b = blockIdx.y, tid = threadIdx.x;
    __shared__ __align__(16) float vec[128];
    __shared__ float rv[128];
    __shared__ int ri[128];
    __shared__ float amp_s;
    __shared__ int jstar_s, astar_s;

    int id = g_topidx[b * 16 + rk];
    float val = g_topval[b * 16 + rk];
    vec[tid] = g_h[(size_t)(b * NF + id) * DM + tid] * val;
    __syncthreads();

    rv[tid] = vec[tid] * amp_w[tid];
    __syncthreads();
    for (int off = 64; off; off >>= 1) {
        if (tid < off) rv[tid] += rv[tid + off];
        __syncthreads();
    }
    if (tid == 0) amp_s = fmaxf(rv[0] + amp_b[0], 0.f);
    __syncthreads();

    const float4* vp = (const float4*)vec;

    float bv = -FLT_MAX; int bi = 1 << 30;
#pragma unroll
    for (int q = 0; q < 4; q++) {
        int o = q * 128 + tid;
        const float4* wp = (const float4*)(pos_w + (size_t)o * DM);
        float lg = pos_b[o];
#pragma unroll
        for (int i = 0; i < 32; i++) {
            float4 w4 = wp[i], v4 = vp[i];
            lg = fmaf(w4.x, v4.x, lg); lg = fmaf(w4.y, v4.y, lg);
            lg = fmaf(w4.z, v4.z, lg); lg = fmaf(w4.w, v4.w, lg);
        }
        if (lg > bv || (lg == bv && o < bi)) { bv = lg; bi = o; }
    }
    rv[tid] = bv; ri[tid] = bi;
    __syncthreads();
    for (int off = 64; off; off >>= 1) {
        if (tid < off) {
            float v2 = rv[tid + off]; int i2 = ri[tid + off];
            if (v2 > rv[tid] || (v2 == rv[tid] && i2 < ri[tid])) { rv[tid] = v2; ri[tid] = i2; }
        }
        __syncthreads();
    }
    if (tid == 0) jstar_s = ri[0];
    __syncthreads();

    bv = -FLT_MAX; bi = 1 << 30;
#pragma unroll
    for (int q = 0; q < 2; q++) {
        int o = q * 128 + tid;
        const float4* wp = (const float4*)(atom_w + (size_t)o * DM);
        float lg = atom_b[o];
#pragma unroll
        for (int i = 0; i < 32; i++) {
            float4 w4 = wp[i], v4 = vp[i];
            lg = fmaf(w4.x, v4.x, lg); lg = fmaf(w4.y, v4.y, lg);
            lg = fmaf(w4.z, v4.z, lg); lg = fmaf(w4.w, v4.w, lg);
        }
        if (lg > bv || (lg == bv && o < bi)) { bv = lg; bi = o; }
    }
    rv[tid] = bv; ri[tid] = bi;
    __syncthreads();
    for (int off = 64; off; off >>= 1) {
        if (tid < off) {
            float v2 = rv[tid + off]; int i2 = ri[tid + off];
            if (v2 > rv[tid] || (v2 == rv[tid] && i2 < ri[tid])) { rv[tid] = v2; ri[tid] = i2; }
        }
        __syncthreads();
    }
    if (tid == 0) astar_s = ri[0];
    __syncthreads();

    float amp = amp_s;
    int p = jstar_s * 64;
    int a = astar_s;
    for (int i = tid; i < 256; i += 128) {
        int t = p + i;
        if (t < NS)
            atomicAdd(out + (size_t)b * NS + t, dmat[(size_t)a * 256 + i] * amp);
    }
}

// ---------------------------------------------------------------------------
extern "C" void kernel_launch(void* const* d_in, const int* in_sizes, int n_in,
                              void* d_out, int out_size)
{
    const float* x         = (const float*)d_in[0];
    const float* fb        = (const float*)d_in[1];
    const float* embed_w   = (const float*)d_in[2];
    const float* embed_b   = (const float*)d_in[3];
    const float* in_proj_w = (const float*)d_in[4];
    const float* in_proj_b = (const float*)d_in[5];
    const float* out_w     = (const float*)d_in[6];
    const float* out_b     = (const float*)d_in[7];
    const float* lin1_w    = (const float*)d_in[8];
    const float* lin1_b    = (const float*)d_in[9];
    const float* lin2_w    = (const float*)d_in[10];
    const float* lin2_b    = (const float*)d_in[11];
    const float* ln1_w     = (const float*)d_in[12];
    const float* ln1_b     = (const float*)d_in[13];
    const float* ln2_w     = (const float*)d_in[14];
    const float* ln2_b     = (const float*)d_in[15];
    const float* attn_w    = (const float*)d_in[16];
    const float* attn_b    = (const float*)d_in[17];
    const float* amp_w     = (const float*)d_in[18];
    const float* amp_b     = (const float*)d_in[19];
    const float* pos_w     = (const float*)d_in[20];
    const float* pos_b     = (const float*)d_in[21];
    const float* atom_w    = (const float*)d_in[22];
    const float* atom_b    = (const float*)d_in[23];
    const float* dmat      = (const float*)d_in[24];
    float* out = (float*)d_out;

    float *p_h, *p_qkv, *p_attno;
    cudaGetSymbolAddress((void**)&p_h, g_h);
    cudaGetSymbolAddress((void**)&p_qkv, g_qkv);
    cudaGetSymbolAddress((void**)&p_attno, g_attno);

    twid_kernel<<<2, 256>>>();
    ewt_kernel<<<(161 * 128 + 255) / 256, 256>>>(embed_w);
    filt_kernel<<<64, 256>>>(fb);
    conv_fft_kernel<<<dim3(64, NB), 256>>>(x);

    embed_kernel<<<NB * NF / 8, 128>>>(embed_b);

    qkv_kernel<<<512, 128>>>(p_h, in_proj_w, in_proj_b, p_qkv);
    for (int i = 0; i < 6; i++) {
        attn_kernel<<<dim3(4, NB), 256>>>();
        const float* Wn = (i < 5) ? in_proj_w + (size_t)(i + 1) * 384 * 128 : nullptr;
        const float* bn = (i < 5) ? in_proj_b + (i + 1) * 384 : nullptr;
        post_kernel<<<512, 128>>>(p_attno,
                                  out_w + (size_t)i * 128 * 128, out_b + i * 128,
                                  ln1_w + i * 128, ln1_b + i * 128,
                                  lin1_w + (size_t)i * 128 * 128, lin1_b + i * 128,
                                  lin2_w + (size_t)i * 128 * 128, lin2_b + i * 128,
                                  ln2_w + i * 128, ln2_b + i * 128, p_h,
                                  Wn, bn, p_qkv);
    }

    topk_kernel<<<NB, 128>>>(attn_w, attn_b);
    cudaMemsetAsync(d_out, 0, (size_t)out_size * sizeof(float), 0);
    scatter_kernel<<<dim3(16, NB), 128>>>(amp_w, amp_b, pos_w, pos_b,
                                          atom_w, atom_b, dmat, out);
}

// round 15
// speedup vs baseline: 1.2886x; 1.1495x over previous
#include <cuda_runtime.h>
#include <math.h>
#include <float.h>

#define NB 32
#define NS 32768
#define NF 128
#define DM 128

// ------------------------- scratch (device globals) -------------------------
__device__ float2 g_twid[512];            // exp(-2*pi*i*k/1024)
__device__ float2 g_P[64 * 1024];         // conj(FFT(w_2c - i w_2c+1)), scrambled
__device__ float g_ewT[161 * 128];        // transposed embed weights
__device__ float g_qkvT[6 * 128 * 384];   // [l][j][o] transposed in_proj
__device__ float g_woT[6 * 128 * 128];
__device__ float g_w1T[6 * 128 * 128];
__device__ float g_w2T[6 * 128 * 128];
__device__ float g_chunk[NB * NF * DM];
__device__ float g_h[NB * NF * DM];
__device__ float g_qkv[NB * NF * 384];
__device__ float g_attno[NB * NF * DM];
__device__ int   g_topidx[NB * 16];
__device__ float g_topval[NB * 16];

// ------------------------- butterflies ---------------------------------------
__device__ __forceinline__ void bf_dif(float& ar, float& ai, float& br, float& bi, float2 w)
{
    float xr = ar - br, xi = ai - bi;
    ar += br; ai += bi;
    br = xr * w.x - xi * w.y;
    bi = xr * w.y + xi * w.x;
}
__device__ __forceinline__ void bf_dit(float& ar, float& ai, float& br, float& bi, float2 w)
{
    float tr = br * w.x + bi * w.y;
    float ti = bi * w.x - br * w.y;
    br = ar - tr; bi = ai - ti;
    ar += tr; ai += ti;
}

// ------------------------- forward 1024-pt DIF (in-place, natural->bitrev) ---
__device__ __forceinline__ void fft1024_dif(float* re, float* im, const float2* tw, int tid)
{
    {
        int r = tid;
        float ar = re[r],       ai = im[r];
        float br = re[r + 256], bi = im[r + 256];
        float cr = re[r + 512], ci = im[r + 512];
        float dr = re[r + 768], di = im[r + 768];
        bf_dif(ar, ai, cr, ci, tw[r]);
        bf_dif(br, bi, dr, di, tw[r + 256]);
        float2 v = tw[2 * r];
        bf_dif(ar, ai, br, bi, v);
        bf_dif(cr, ci, dr, di, v);
        re[r] = ar;       im[r] = ai;
        re[r + 256] = br; im[r + 256] = bi;
        re[r + 512] = cr; im[r + 512] = ci;
        re[r + 768] = dr; im[r + 768] = di;
    }
    __syncthreads();
    {
        int q = tid >> 6, r = tid & 63, i0 = q * 256 + r;
        float ar = re[i0],       ai = im[i0];
        float br = re[i0 + 64],  bi = im[i0 + 64];
        float cr = re[i0 + 128], ci = im[i0 + 128];
        float dr = re[i0 + 192], di = im[i0 + 192];
        bf_dif(ar, ai, cr, ci, tw[4 * r]);
        bf_dif(br, bi, dr, di, tw[4 * r + 256]);
        float2 v = tw[8 * r];
        bf_dif(ar, ai, br, bi, v);
        bf_dif(cr, ci, dr, di, v);
        re[i0] = ar;       im[i0] = ai;
        re[i0 + 64] = br;  im[i0 + 64] = bi;
        re[i0 + 128] = cr; im[i0 + 128] = ci;
        re[i0 + 192] = dr; im[i0 + 192] = di;
    }
    __syncthreads();
    {
        float4 R = ((const float4*)re)[tid];
        float4 I = ((const float4*)im)[tid];
        float vr[4] = {R.x, R.y, R.z, R.w};
        float vi[4] = {I.x, I.y, I.z, I.w};
#pragma unroll
        for (int s = 3; s >= 0; s--) {
            const int mask = 1 << s;
            const int step = 128 >> s;
            const int kb = 4 * (tid & (mask - 1));
            const bool up = (tid & mask) != 0;
#pragma unroll
            for (int j = 0; j < 4; j++) {
                float orr = __shfl_xor_sync(0xffffffffu, vr[j], mask);
                float oii = __shfl_xor_sync(0xffffffffu, vi[j], mask);
                float2 w = tw[(kb + j) * step];
                float sr = vr[j] + orr, si = vi[j] + oii;
                float dr = orr - vr[j], di = oii - vi[j];
                float pr = dr * w.x - di * w.y;
                float pi = dr * w.y + di * w.x;
                vr[j] = up ? pr : sr;
                vi[j] = up ? pi : si;
            }
        }
        {
            float s0r = vr[0] + vr[2], s0i = vi[0] + vi[2];
            float d0r = vr[0] - vr[2], d0i = vi[0] - vi[2];
            vr[0] = s0r; vi[0] = s0i; vr[2] = d0r; vi[2] = d0i;
            float s1r = vr[1] + vr[3], s1i = vi[1] + vi[3];
            float d1r = vr[1] - vr[3], d1i = vi[1] - vi[3];
            vr[1] = s1r; vi[1] = s1i;
            vr[3] = d1i; vi[3] = -d1r;
        }
        {
            float t0r = vr[0] + vr[1], t0i = vi[0] + vi[1];
            float t1r = vr[0] - vr[1], t1i = vi[0] - vi[1];
            float t2r = vr[2] + vr[3], t2i = vi[2] + vi[3];
            float t3r = vr[2] - vr[3], t3i = vi[2] - vi[3];
            vr[0] = t0r; vi[0] = t0i; vr[1] = t1r; vi[1] = t1i;
            vr[2] = t2r; vi[2] = t2i; vr[3] = t3r; vi[3] = t3i;
        }
        ((float4*)re)[tid] = make_float4(vr[0], vr[1], vr[2], vr[3]);
        ((float4*)im)[tid] = make_float4(vi[0], vi[1], vi[2], vi[3]);
    }
    __syncthreads();
}

// ------------------------- precompute kernels --------------------------------
__global__ void twid_kernel()
{
    int k = blockIdx.x * 256 + threadIdx.x;
    if (k < 512) {
        double a = -2.0 * 3.14159265358979323846 * (double)k / 1024.0;
        g_twid[k] = make_float2((float)cos(a), (float)sin(a));
    }
}

__global__ __launch_bounds__(256) void filt_kernel(const float* __restrict__ fb)
{
    __shared__ __align__(16) float re[1024], im[1024];
    __shared__ __align__(16) float2 tw[512];
    const int c = blockIdx.x, tid = threadIdx.x;
    tw[tid] = g_twid[tid]; tw[tid + 256] = g_twid[tid + 256];
    for (int i = tid; i < 1024; i += 256) {
        re[i] = (i < 512) ? fb[(size_t)(2 * c) * 512 + i] : 0.f;
        im[i] = (i < 512) ? -fb[(size_t)(2 * c + 1) * 512 + i] : 0.f;
    }
    __syncthreads();
    fft1024_dif(re, im, tw, tid);
    for (int i = tid; i < 1024; i += 256)
        g_P[(size_t)c * 1024 + i] = make_float2(re[i], -im[i]);
}

__global__ void ewt_kernel(const float* __restrict__ ew)
{
    int i = blockIdx.x * 256 + threadIdx.x;
    if (i < 161 * 128) {
        int j = i >> 7, c = i & 127;
        g_ewT[j * 128 + c] = ew[(size_t)c * 161 + j];
    }
}

// transpose in_proj: src [l][o(384)][j(128)] -> dst [l][j][o]
__global__ void tq_kernel(const float* __restrict__ src)
{
    int i = blockIdx.x * 256 + threadIdx.x;
    if (i < 6 * 384 * 128) {
        int l = i / 49152, rem = i % 49152;
        int o = rem >> 7, j = rem & 127;
        g_qkvT[(size_t)l * 49152 + j * 384 + o] = src[i];
    }
}
// transpose square: src [l][o(128)][j(128)] -> dst [l][j][o]
__global__ void ts_kernel(const float* __restrict__ src, float* __restrict__ dst)
{
    int i = blockIdx.x * 256 + threadIdx.x;
    if (i < 6 * 128 * 128) {
        int l = i / 16384, rem = i % 16384;
        int o = rem >> 7, j = rem & 127;
        dst[(size_t)l * 16384 + j * 128 + o] = src[i];
    }
}

// ---- trip A: fused pointwise(U*P) + DIT stages 1..64; result to z slot -------
__device__ __forceinline__ void ifft_stageA(const float ur[4], const float ui[4],
                                            const float4* __restrict__ Pp,
                                            const float2* twA, int tid,
                                            float* zr, float* zi)
{
    float4 P0 = Pp[2 * tid], P1 = Pp[2 * tid + 1];
    float vr[4], vi[4];
    vr[0] = ur[0] * P0.x - ui[0] * P0.y; vi[0] = ur[0] * P0.y + ui[0] * P0.x;
    vr[1] = ur[1] * P0.z - ui[1] * P0.w; vi[1] = ur[1] * P0.w + ui[1] * P0.z;
    vr[2] = ur[2] * P1.x - ui[2] * P1.y; vi[2] = ur[2] * P1.y + ui[2] * P1.x;
    vr[3] = ur[3] * P1.z - ui[3] * P1.w; vi[3] = ur[3] * P1.w + ui[3] * P1.z;
    {
        float t0r = vr[0] + vr[1], t0i = vi[0] + vi[1];
        float t1r = vr[0] - vr[1], t1i = vi[0] - vi[1];
        float t2r = vr[2] + vr[3], t2i = vi[2] + vi[3];
        float t3r = vr[2] - vr[3], t3i = vi[2] - vi[3];
        vr[0] = t0r; vi[0] = t0i; vr[1] = t1r; vi[1] = t1i;
        vr[2] = t2r; vi[2] = t2i; vr[3] = t3r; vi[3] = t3i;
    }
    {
        float s0r = vr[0] + vr[2], s0i = vi[0] + vi[2];
        float d0r = vr[0] - vr[2], d0i = vi[0] - vi[2];
        vr[0] = s0r; vi[0] = s0i; vr[2] = d0r; vi[2] = d0i;
        float tr = -vi[3], ti = vr[3];
        float nr = vr[1] + tr, ni = vi[1] + ti;
        float mr = vr[1] - tr, mi = vi[1] - ti;
        vr[1] = nr; vi[1] = ni; vr[3] = mr; vi[3] = mi;
    }
#pragma unroll
    for (int s = 0; s < 5; s++) {
        const int mask = 1 << s;
        const int offA = 4 * (mask - 1);
        const int ib = tid & (mask - 1);
#pragma unroll
        for (int j = 0; j < 4; j++) {
            float orr = __shfl_xor_sync(0xffffffffu, vr[j], mask);
            float oii = __shfl_xor_sync(0xffffffffu, vi[j], mask);
            float2 tww = twA[offA + (j << s) + ib];
            const bool up = (tid & mask) != 0;
            float sr = up ? vr[j] : orr;
            float sI = up ? vi[j] : oii;
            float tr = sr * tww.x + sI * tww.y;
            float ti = sI * tww.x - sr * tww.y;
            float lr = vr[j] + tr, li = vi[j] + ti;
            float ur_ = orr - tr, ui_ = oii - ti;
            vr[j] = up ? ur_ : lr;
            vi[j] = up ? ui_ : li;
        }
    }
    ((float4*)zr)[tid] = make_float4(vr[0], vr[1], vr[2], vr[3]);
    ((float4*)zi)[tid] = make_float4(vi[0], vi[1], vi[2], vi[3]);
}

// ------------------------- FFT conv + |.| + pool -----------------------------
__global__ __launch_bounds__(256) void conv_fft_kernel(const float* __restrict__ x)
{
    __shared__ __align__(16) float uRe[1024], uIm[1024];
    __shared__ __align__(16) float zRe[2048], zIm[2048];
    __shared__ __align__(16) float2 tw[512];
    __shared__ __align__(16) float2 twA[124];
    __shared__ float cs0[128], cs1[128];
    __shared__ float wpart[2][4][4];
    const int seg = blockIdx.x, b = blockIdx.y;
    const int tid = threadIdx.x, w = tid >> 5, lane = tid & 31;

    tw[tid] = g_twid[tid]; tw[tid + 256] = g_twid[tid + 256];
    if (tid < 124) {
        int e = tid, s, base0;
        if (e < 4)       { s = 0; base0 = 0; }
        else if (e < 12) { s = 1; base0 = 4; }
        else if (e < 28) { s = 2; base0 = 12; }
        else if (e < 60) { s = 3; base0 = 28; }
        else             { s = 4; base0 = 60; }
        int r = e - base0;
        int j = r >> s;
        int i = r & ((1 << s) - 1);
        twA[e] = g_twid[(4 * i + j) * (128 >> s)];
    }
    const float* xb = x + (size_t)b * NS;
    const int base = seg * 512 - 256;
    for (int i = tid; i < 1024; i += 256) {
        int g = base + i;
        uRe[i] = (g >= 0 && g < NS) ? xb[g] : 0.f;
        uIm[i] = 0.f;
    }
    if (tid < 128) { cs0[tid] = 0.f; cs1[tid] = 0.f; }
    __syncthreads();
    fft1024_dif(uRe, uIm, tw, tid);

    float ur[4], ui[4];
    {
        float4 R = ((const float4*)uRe)[tid];
        float4 I = ((const float4*)uIm)[tid];
        ur[0] = R.x; ur[1] = R.y; ur[2] = R.z; ur[3] = R.w;
        ui[0] = I.x; ui[1] = I.y; ui[2] = I.z; ui[3] = I.w;
    }
    const int rB = tid & 127;
    const float2 t4r  = tw[4 * rB];
    const float2 t2r  = tw[2 * rB];
    const float2 t2r2 = tw[2 * rB + 256];
    const float2 t5a = tw[rB], t5b = tw[rB + 128], t5c = tw[rB + 256], t5d = tw[rB + 384];

    for (int p = 0; p < 64; p += 2) {
        ifft_stageA(ur, ui, (const float4*)(g_P + (size_t)p * 1024), twA, tid, zRe, zIm);
        ifft_stageA(ur, ui, (const float4*)(g_P + (size_t)(p + 1) * 1024), twA, tid,
                    zRe + 1024, zIm + 1024);
        __syncthreads();

        const int s = tid >> 7;
        const float* zr = zRe + (s << 10);
        const float* zi = zIm + (s << 10);
        float xr[8], xi[8];
#pragma unroll
        for (int k = 0; k < 8; k++) { xr[k] = zr[rB + (k << 7)]; xi[k] = zi[rB + (k << 7)]; }
        bf_dit(xr[0], xi[0], xr[1], xi[1], t4r);
        bf_dit(xr[2], xi[2], xr[3], xi[3], t4r);
        bf_dit(xr[4], xi[4], xr[5], xi[5], t4r);
        bf_dit(xr[6], xi[6], xr[7], xi[7], t4r);
        bf_dit(xr[0], xi[0], xr[2], xi[2], t2r);
        bf_dit(xr[1], xi[1], xr[3], xi[3], t2r2);
        bf_dit(xr[4], xi[4], xr[6], xi[6], t2r);
        bf_dit(xr[5], xi[5], xr[7], xi[7], t2r2);
        {
            float tr, ti;
            tr = xr[4] * t5a.x + xi[4] * t5a.y; ti = xi[4] * t5a.x - xr[4] * t5a.y;
            xr[0] += tr; xi[0] += ti;
            tr = xr[5] * t5b.x + xi[5] * t5b.y; ti = xi[5] * t5b.x - xr[5] * t5b.y;
            xr[1] += tr; xi[1] += ti;
            tr = xr[6] * t5c.x + xi[6] * t5c.y; ti = xi[6] * t5c.x - xr[6] * t5c.y;
            xr[2] += tr; xi[2] += ti;
            tr = xr[7] * t5d.x + xi[7] * t5d.y; ti = xi[7] * t5d.x - xr[7] * t5d.y;
            xr[3] += tr; xi[3] += ti;
        }
        float v0 = fabsf(xr[0]) + fabsf(xr[1]);
        float v1 = fabsf(xi[0]) + fabsf(xi[1]);
        float v2 = fabsf(xr[2]) + fabsf(xr[3]);
        float v3 = fabsf(xi[2]) + fabsf(xi[3]);
#pragma unroll
        for (int o = 16; o; o >>= 1) {
            v0 += __shfl_xor_sync(0xffffffffu, v0, o);
            v1 += __shfl_xor_sync(0xffffffffu, v1, o);
            v2 += __shfl_xor_sync(0xffffffffu, v2, o);
            v3 += __shfl_xor_sync(0xffffffffu, v3, o);
        }
        if (lane == 0) {
            wpart[s][w & 3][0] = v0; wpart[s][w & 3][1] = v1;
            wpart[s][w & 3][2] = v2; wpart[s][w & 3][3] = v3;
        }
        __syncthreads();
        if (tid < 8) {
            int pr = tid >> 2, q = tid & 3;
            float sm = wpart[pr][0][q] + wpart[pr][1][q] + wpart[pr][2][q] + wpart[pr][3][q];
            int pp = p + pr;
            if (q == 0)      cs0[2 * pp]     += sm;
            else if (q == 1) cs0[2 * pp + 1] += sm;
            else if (q == 2) cs1[2 * pp]     += sm;
            else             cs1[2 * pp + 1] += sm;
        }
        __syncthreads();
    }
    const float scale = 1.f / (1024.f * 512.f);
    if (tid < 128) {
        g_chunk[((size_t)b * NF + 2 * seg) * DM + tid]     = cs0[tid] * scale;
        g_chunk[((size_t)b * NF + 2 * seg + 1) * DM + tid] = cs1[tid] * scale;
    }
}

// ---------------- frames + pos-encoding + embed (8 rows / block) -------------
__global__ __launch_bounds__(128) void embed_kernel(const float* __restrict__ eb)
{
    const int row0 = blockIdx.x << 3;
    const int tid = threadIdx.x;
    __shared__ float vec[8][161];
    for (int idx = tid; idx < 1024; idx += 128) {
        int r = idx >> 7, ch = idx & 127;
        int row = row0 + r, t = row & 127;
        float f = g_chunk[(size_t)row * DM + ch];
        if (t > 0) f += g_chunk[(size_t)(row - 1) * DM + ch];
        vec[r][ch] = f;
    }
    for (int idx = tid; idx < 264; idx += 128) {
        int r = idx / 33, kk = idx % 33;
        int t = (row0 + r) & 127;
        float pos = (t == 127) ? 1.0f
                               : __fadd_rn(-1.0f, __fmul_rn((float)t, __fdiv_rn(2.0f, 127.0f)));
        float v;
        if (kk == 0) v = pos;
        else {
            int k = (kk <= 16) ? (kk - 1) : (kk - 17);
            float fr = __fmul_rn(exp2f((float)k), 3.14159274101257324f);
            float prod = __fmul_rn(pos, fr);
            v = (kk <= 16) ? (float)sin((double)prod) : (float)cos((double)prod);
        }
        vec[r][128 + kk] = v;
    }
    __syncthreads();
    float acc[8];
    float bv = eb[tid];
#pragma unroll
    for (int r = 0; r < 8; r++) acc[r] = bv;
    for (int j = 0; j < 161; j++) {
        float wv = g_ewT[j * 128 + tid];
#pragma unroll
        for (int r = 0; r < 8; r++) acc[r] = fmaf(vec[r][j], wv, acc[r]);
    }
#pragma unroll
    for (int r = 0; r < 8; r++)
        g_h[(size_t)(row0 + r) * DM + tid] = acc[r];
}

// ---------------- qkv linear (transposed weights, coalesced) -----------------
__global__ __launch_bounds__(128) void qkv_kernel(const float* __restrict__ in,
                                                  const float* __restrict__ WT,
                                                  const float* __restrict__ bias,
                                                  float* __restrict__ out)
{
    const int row0 = blockIdx.x << 3;
    const int tid = threadIdx.x;
    __shared__ __align__(16) float sv[8 * DM];
#pragma unroll
    for (int r = 0; r < 8; r++) sv[r * DM + tid] = in[(size_t)(row0 + r) * DM + tid];
    __syncthreads();
    float acc[3][8];
#pragma unroll
    for (int o = 0; o < 3; o++) {
        float bv = bias[o * DM + tid];
#pragma unroll
        for (int r = 0; r < 8; r++) acc[o][r] = bv;
    }
    const float4* sv4 = (const float4*)sv;
    for (int j4 = 0; j4 < 32; j4++) {
        float wv[3][4];
#pragma unroll
        for (int k = 0; k < 4; k++) {
            const float* wp = WT + (size_t)(4 * j4 + k) * 384 + tid;
#pragma unroll
            for (int o = 0; o < 3; o++) wv[o][k] = wp[o * 128];
        }
#pragma unroll
        for (int r = 0; r < 8; r++) {
            float4 xv = sv4[r * 32 + j4];
#pragma unroll
            for (int o = 0; o < 3; o++) {
                acc[o][r] = fmaf(wv[o][0], xv.x, acc[o][r]);
                acc[o][r] = fmaf(wv[o][1], xv.y, acc[o][r]);
                acc[o][r] = fmaf(wv[o][2], xv.z, acc[o][r]);
                acc[o][r] = fmaf(wv[o][3], xv.w, acc[o][r]);
            }
        }
    }
#pragma unroll
    for (int r = 0; r < 8; r++)
#pragma unroll
        for (int o = 0; o < 3; o++)
            out[(size_t)(row0 + r) * 384 + o * DM + tid] = acc[o][r];
}

// ---------------- attention: split-K, one CTA per (head, batch) --------------
__global__ __launch_bounds__(256) void attn_kernel()
{
    const int hd = blockIdx.x, b = blockIdx.y;
    const int tid = threadIdx.x;
    const int half = tid >> 7, qi = tid & 127;
    __shared__ __align__(16) float ks[NF * 32];
    __shared__ __align__(16) float vs[NF * 32];
    const float* base = g_qkv + (size_t)b * NF * 384;

    for (int idx = tid; idx < NF * 32; idx += 256) {
        int j = idx >> 5, i = idx & 31;
        ks[idx] = base[j * 384 + 128 + hd * 32 + i];
        vs[idx] = base[j * 384 + 256 + hd * 32 + i];
    }
    float q[32];
    {
        const float4* qp = (const float4*)(base + (size_t)qi * 384 + hd * 32);
#pragma unroll
        for (int i = 0; i < 8; i++) {
            float4 v = qp[i];
            q[4 * i] = v.x; q[4 * i + 1] = v.y; q[4 * i + 2] = v.z; q[4 * i + 3] = v.w;
        }
    }
    __syncthreads();

    float o[32];
#pragma unroll
    for (int i = 0; i < 32; i++) o[i] = 0.f;
    float m = -FLT_MAX, l = 0.f;
    const float scale = 0.17677669529663689f;
    const int j0 = half << 6;

    for (int j = j0; j < j0 + 64; j += 2) {
        const float4* kp1 = (const float4*)(ks + j * 32);
        const float4* kp2 = (const float4*)(ks + j * 32 + 32);
        float s1 = 0.f, s2 = 0.f;
#pragma unroll
        for (int i = 0; i < 8; i++) {
            float4 k1 = kp1[i], k2 = kp2[i];
            s1 = fmaf(q[4 * i], k1.x, s1); s2 = fmaf(q[4 * i], k2.x, s2);
            s1 = fmaf(q[4 * i + 1], k1.y, s1); s2 = fmaf(q[4 * i + 1], k2.y, s2);
            s1 = fmaf(q[4 * i + 2], k1.z, s1); s2 = fmaf(q[4 * i + 2], k2.z, s2);
            s1 = fmaf(q[4 * i + 3], k1.w, s1); s2 = fmaf(q[4 * i + 3], k2.w, s2);
        }
        s1 *= scale; s2 *= scale;
        float mn = fmaxf(m, fmaxf(s1, s2));
        float c = expf(m - mn);
        float p1 = expf(s1 - mn);
        float p2 = expf(s2 - mn);
        l = l * c + p1 + p2;
        const float4* vp1 = (const float4*)(vs + j * 32);
        const float4* vp2 = (const float4*)(vs + j * 32 + 32);
#pragma unroll
        for (int i = 0; i < 8; i++) {
            float4 v1 = vp1[i], v2 = vp2[i];
            o[4 * i]     = fmaf(p2, v2.x, fmaf(p1, v1.x, o[4 * i] * c));
            o[4 * i + 1] = fmaf(p2, v2.y, fmaf(p1, v1.y, o[4 * i + 1] * c));
            o[4 * i + 2] = fmaf(p2, v2.z, fmaf(p1, v1.z, o[4 * i + 2] * c));
            o[4 * i + 3] = fmaf(p2, v2.w, fmaf(p1, v1.w, o[4 * i + 3] * c));
        }
        m = mn;
    }
    __syncthreads();
    if (half == 1) {
        vs[qi] = m; vs[128 + qi] = l;
#pragma unroll
        for (int i = 0; i < 32; i++) ks[i * 128 + qi] = o[i];
    }
    __syncthreads();
    if (half == 0) {
        float m2 = vs[qi], l2 = vs[128 + qi];
        float mn = fmaxf(m, m2);
        float c1 = expf(m - mn), c2 = expf(m2 - mn);
        float inv = 1.f / (l * c1 + l2 * c2);
        float* dst = g_attno + (size_t)(b * NF + qi) * DM + hd * 32;
#pragma unroll
        for (int i = 0; i < 32; i++)
            dst[i] = (o[i] * c1 + ks[i * 128 + qi] * c2) * inv;
    }
}

// ---------------- LN epilogues ------------------------------------------------
__device__ __forceinline__ void ln_to_gmem(float v[8], const float* lnw, const float* lnb,
                                           float* h, int row0, int tid)
{
    __shared__ float red[4][8];
    const int w = tid >> 5;
    float mean[8];
#pragma unroll
    for (int r = 0; r < 8; r++) {
        float s = v[r];
#pragma unroll
        for (int o = 16; o; o >>= 1) s += __shfl_xor_sync(0xffffffffu, s, o);
        if ((tid & 31) == 0) red[w][r] = s;
    }
    __syncthreads();
#pragma unroll
    for (int r = 0; r < 8; r++)
        mean[r] = (red[0][r] + red[1][r] + red[2][r] + red[3][r]) * 0.0078125f;
    __syncthreads();
#pragma unroll
    for (int r = 0; r < 8; r++) {
        float dv = v[r] - mean[r];
        float s = dv * dv;
#pragma unroll
        for (int o = 16; o; o >>= 1) s += __shfl_xor_sync(0xffffffffu, s, o);
        if ((tid & 31) == 0) red[w][r] = s;
        v[r] = dv;
    }
    __syncthreads();
    float lw = lnw[tid], lb = lnb[tid];
#pragma unroll
    for (int r = 0; r < 8; r++) {
        float var = (red[0][r] + red[1][r] + red[2][r] + red[3][r]) * 0.0078125f;
        h[(size_t)(row0 + r) * DM + tid] = v[r] * (1.f / sqrtf(var + 1e-5f)) * lw + lb;
    }
}

__device__ __forceinline__ void ln_to_smem(float v[8], const float* lnw, const float* lnb,
                                           float* dst, int tid)
{
    __shared__ float red2[4][8];
    const int w = tid >> 5;
    float mean[8];
#pragma unroll
    for (int r = 0; r < 8; r++) {
        float s = v[r];
#pragma unroll
        for (int o = 16; o; o >>= 1) s += __shfl_xor_sync(0xffffffffu, s, o);
        if ((tid & 31) == 0) red2[w][r] = s;
    }
    __syncthreads();
#pragma unroll
    for (int r = 0; r < 8; r++)
        mean[r] = (red2[0][r] + red2[1][r] + red2[2][r] + red2[3][r]) * 0.0078125f;
    __syncthreads();
#pragma unroll
    for (int r = 0; r < 8; r++) {
        float dv = v[r] - mean[r];
        float s = dv * dv;
#pragma unroll
        for (int o = 16; o; o >>= 1) s += __shfl_xor_sync(0xffffffffu, s, o);
        if ((tid & 31) == 0) red2[w][r] = s;
        v[r] = dv;
    }
    __syncthreads();
    float lw = lnw[tid], lb = lnb[tid];
#pragma unroll
    for (int r = 0; r < 8; r++) {
        float var = (red2[0][r] + red2[1][r] + red2[2][r] + red2[3][r]) * 0.0078125f;
        dst[r * DM + tid] = v[r] * (1.f / sqrtf(var + 1e-5f)) * lw + lb;
    }
}

__device__ __forceinline__ void ln_to_both(float v[8], const float* lnw, const float* lnb,
                                           float* h, int row0, float* dst, int tid)
{
    __shared__ float red3[4][8];
    const int w = tid >> 5;
    float mean[8];
#pragma unroll
    for (int r = 0; r < 8; r++) {
        float s = v[r];
#pragma unroll
        for (int o = 16; o; o >>= 1) s += __shfl_xor_sync(0xffffffffu, s, o);
        if ((tid & 31) == 0) red3[w][r] = s;
    }
    __syncthreads();
#pragma unroll
    for (int r = 0; r < 8; r++)
        mean[r] = (red3[0][r] + red3[1][r] + red3[2][r] + red3[3][r]) * 0.0078125f;
    __syncthreads();
#pragma unroll
    for (int r = 0; r < 8; r++) {
        float dv = v[r] - mean[r];
        float s = dv * dv;
#pragma unroll
        for (int o = 16; o; o >>= 1) s += __shfl_xor_sync(0xffffffffu, s, o);
        if ((tid & 31) == 0) red3[w][r] = s;
        v[r] = dv;
    }
    __syncthreads();
    float lw = lnw[tid], lb = lnb[tid];
#pragma unroll
    for (int r = 0; r < 8; r++) {
        float var = (red3[0][r] + red3[1][r] + red3[2][r] + red3[3][r]) * 0.0078125f;
        float outv = v[r] * (1.f / sqrtf(var + 1e-5f)) * lw + lb;
        h[(size_t)(row0 + r) * DM + tid] = outv;
        dst[r * DM + tid] = outv;
    }
}

// square GEMM pass with transposed weights: acc[r] = bias + sum_j WT[j][tid]*src[r][j]
__device__ __forceinline__ void gemm_sq(const float* __restrict__ WT, float bv,
                                        const float4* sv4, float acc[8], int tid)
{
#pragma unroll
    for (int r = 0; r < 8; r++) acc[r] = bv;
    for (int j4 = 0; j4 < 32; j4++) {
        float w0 = WT[(size_t)(4 * j4 + 0) * 128 + tid];
        float w1 = WT[(size_t)(4 * j4 + 1) * 128 + tid];
        float w2 = WT[(size_t)(4 * j4 + 2) * 128 + tid];
        float w3 = WT[(size_t)(4 * j4 + 3) * 128 + tid];
#pragma unroll
        for (int r = 0; r < 8; r++) {
            float4 xv = sv4[r * 32 + j4];
            acc[r] = fmaf(w0, xv.x, acc[r]);
            acc[r] = fmaf(w1, xv.y, acc[r]);
            acc[r] = fmaf(w2, xv.z, acc[r]);
            acc[r] = fmaf(w3, xv.w, acc[r]);
        }
    }
}

// ---------------- post: proj+res+LN1+FFN+res+LN2 (+ next-layer qkv) ----------
__global__ __launch_bounds__(128) void post_kernel(const float* __restrict__ in,
                                                   const float* __restrict__ WoT,
                                                   const float* __restrict__ bo,
                                                   const float* __restrict__ ln1w,
                                                   const float* __restrict__ ln1b,
                                                   const float* __restrict__ W1T,
                                                   const float* __restrict__ b1,
                                                   const float* __restrict__ W2T,
                                                   const float* __restrict__ b2,
                                                   const float* __restrict__ ln2w,
                                                   const float* __restrict__ ln2b,
                                                   float* __restrict__ h,
                                                   const float* __restrict__ WnT,
                                                   const float* __restrict__ bn,
                                                   float* __restrict__ qkv_out)
{
    const int row0 = blockIdx.x << 3;
    const int tid = threadIdx.x;
    __shared__ __align__(16) float sv[8 * DM];
    __shared__ __align__(16) float s1[8 * DM];
#pragma unroll
    for (int r = 0; r < 8; r++) sv[r * DM + tid] = in[(size_t)(row0 + r) * DM + tid];
    __syncthreads();

    float acc[8];
    gemm_sq(WoT, bo[tid], (const float4*)sv, acc, tid);
    float v[8];
#pragma unroll
    for (int r = 0; r < 8; r++) v[r] = h[(size_t)(row0 + r) * DM + tid] + acc[r];
    ln_to_smem(v, ln1w, ln1b, sv, tid);
    __syncthreads();
    gemm_sq(W1T, b1[tid], (const float4*)sv, acc, tid);
#pragma unroll
    for (int r = 0; r < 8; r++) s1[r * DM + tid] = fmaxf(acc[r], 0.f);
    __syncthreads();
    gemm_sq(W2T, b2[tid], (const float4*)s1, acc, tid);
#pragma unroll
    for (int r = 0; r < 8; r++) v[r] = sv[r * DM + tid] + acc[r];

    if (WnT == nullptr) {
        ln_to_gmem(v, ln2w, ln2b, h, row0, tid);
        return;
    }
    ln_to_both(v, ln2w, ln2b, h, row0, sv, tid);
    __syncthreads();

    float accq[3][8];
#pragma unroll
    for (int o = 0; o < 3; o++) {
        float bv = bn[o * DM + tid];
#pragma unroll
        for (int r = 0; r < 8; r++) accq[o][r] = bv;
    }
    const float4* sv4 = (const float4*)sv;
    for (int j4 = 0; j4 < 32; j4++) {
        float wv[3][4];
#pragma unroll
        for (int k = 0; k < 4; k++) {
            const float* wp = WnT + (size_t)(4 * j4 + k) * 384 + tid;
#pragma unroll
            for (int o = 0; o < 3; o++) wv[o][k] = wp[o * 128];
        }
#pragma unroll
        for (int r = 0; r < 8; r++) {
            float4 xv = sv4[r * 32 + j4];
#pragma unroll
            for (int o = 0; o < 3; o++) {
                accq[o][r] = fmaf(wv[o][0], xv.x, accq[o][r]);
                accq[o][r] = fmaf(wv[o][1], xv.y, accq[o][r]);
                accq[o][r] = fmaf(wv[o][2], xv.z, accq[o][r]);
                accq[o][r] = fmaf(wv[o][3], xv.w, accq[o][r]);
            }
        }
    }
#pragma unroll
    for (int r = 0; r < 8; r++)
#pragma unroll
        for (int o = 0; o < 3; o++)
            qkv_out[(size_t)(row0 + r) * 384 + o * DM + tid] = accq[o][r];
}

// ---------------- attention scores + top-16 ---------------------------------
__global__ __launch_bounds__(128) void topk_kernel(const float* __restrict__ attn_w,
                                                   const float* __restrict__ attn_b)
{
    const int b = blockIdx.x, tid = threadIdx.x;
    __shared__ float sv[128];
    __shared__ float rv[128];
    __shared__ int ri[128];
    const float4* hp = (const float4*)(g_h + (size_t)(b * NF + tid) * DM);
    const float4* wp = (const float4*)attn_w;
    float s = attn_b[0];
#pragma unroll
    for (int i = 0; i < 32; i++) {
        float4 h4 = hp[i], w4 = wp[i];
        s = fmaf(h4.x, w4.x, s); s = fmaf(h4.y, w4.y, s);
        s = fmaf(h4.z, w4.z, s); s = fmaf(h4.w, w4.w, s);
    }
    sv[tid] = s;
    __syncthreads();
    for (int r = 0; r < 16; r++) {
        rv[tid] = sv[tid]; ri[tid] = tid;
        __syncthreads();
        for (int off = 64; off; off >>= 1) {
            if (tid < off) {
                float v2 = rv[tid + off]; int i2 = ri[tid + off];
                if (v2 > rv[tid] || (v2 == rv[tid] && i2 < ri[tid])) { rv[tid] = v2; ri[tid] = i2; }
            }
            __syncthreads();
        }
        if (tid == 0) {
            g_topidx[b * 16 + r] = ri[0];
            g_topval[b * 16 + r] = rv[0];
            sv[ri[0]] = -FLT_MAX;
        }
        __syncthreads();
    }
}

// ---------------- head: amp, pos/atom argmax, scatter -----------------------
__global__ __launch_bounds__(128) void scatter_kernel(const float* __restrict__ amp_w,
                                                      const float* __restrict__ amp_b,
                                                      const float* __restrict__ pos_w,
                                                      const float* __restrict__ pos_b,
                                                      const float* __restrict__ atom_w,
                                                      const float* __restrict__ atom_b,
                                                      const float* __restrict__ dmat,
                                                      float* __restrict__ out)
{
    const int rk = blockIdx.x, b = blockIdx.y, tid = threadIdx.x;
    __shared__ __align__(16) float vec[128];
    __shared__ float rv[128];
    __shared__ int ri[128];
    __shared__ float amp_s;
    __shared__ int jstar_s, astar_s;

    int id = g_topidx[b * 16 + rk];
    float val = g_topval[b * 16 + rk];
    vec[tid] = g_h[(size_t)(b * NF + id) * DM + tid] * val;
    __syncthreads();

    rv[tid] = vec[tid] * amp_w[tid];
    __syncthreads();
    for (int off = 64; off; off >>= 1) {
        if (tid < off) rv[tid] += rv[tid + off];
        __syncthreads();
    }
    if (tid == 0) amp_s = fmaxf(rv[0] + amp_b[0], 0.f);
    __syncthreads();

    const float4* vp = (const float4*)vec;

    float bv = -FLT_MAX; int bi = 1 << 30;
#pragma unroll
    for (int q = 0; q < 4; q++) {
        int o = q * 128 + tid;
        const float4* wp = (const float4*)(pos_w + (size_t)o * DM);
        float lg = pos_b[o];
#pragma unroll
        for (int i = 0; i < 32; i++) {
            float4 w4 = wp[i], v4 = vp[i];
            lg = fmaf(w4.x, v4.x, lg); lg = fmaf(w4.y, v4.y, lg);
            lg = fmaf(w4.z, v4.z, lg); lg = fmaf(w4.w, v4.w, lg);
        }
        if (lg > bv || (lg == bv && o < bi)) { bv = lg; bi = o; }
    }
    rv[tid] = bv; ri[tid] = bi;
    __syncthreads();
    for (int off = 64; off; off >>= 1) {
        if (tid < off) {
            float v2 = rv[tid + off]; int i2 = ri[tid + off];
            if (v2 > rv[tid] || (v2 == rv[tid] && i2 < ri[tid])) { rv[tid] = v2; ri[tid] = i2; }
        }
        __syncthreads();
    }
    if (tid == 0) jstar_s = ri[0];
    __syncthreads();

    bv = -FLT_MAX; bi = 1 << 30;
#pragma unroll
    for (int q = 0; q < 2; q++) {
        int o = q * 128 + tid;
        const float4* wp = (const float4*)(atom_w + (size_t)o * DM);
        float lg = atom_b[o];
#pragma unroll
        for (int i = 0; i < 32; i++) {
            float4 w4 = wp[i], v4 = vp[i];
            lg = fmaf(w4.x, v4.x, lg); lg = fmaf(w4.y, v4.y, lg);
            lg = fmaf(w4.z, v4.z, lg); lg = fmaf(w4.w, v4.w, lg);
        }
        if (lg > bv || (lg == bv && o < bi)) { bv = lg; bi = o; }
    }
    rv[tid] = bv; ri[tid] = bi;
    __syncthreads();
    for (int off = 64; off; off >>= 1) {
        if (tid < off) {
            float v2 = rv[tid + off]; int i2 = ri[tid + off];
            if (v2 > rv[tid] || (v2 == rv[tid] && i2 < ri[tid])) { rv[tid] = v2; ri[tid] = i2; }
        }
        __syncthreads();
    }
    if (tid == 0) astar_s = ri[0];
    __syncthreads();

    float amp = amp_s;
    int p = jstar_s * 64;
    int a = astar_s;
    for (int i = tid; i < 256; i += 128) {
        int t = p + i;
        if (t < NS)
            atomicAdd(out + (size_t)b * NS + t, dmat[(size_t)a * 256 + i] * amp);
    }
}

// ---------------------------------------------------------------------------
extern "C" void kernel_launch(void* const* d_in, const int* in_sizes, int n_in,
                              void* d_out, int out_size)
{
    const float* x         = (const float*)d_in[0];
    const float* fb        = (const float*)d_in[1];
    const float* embed_w   = (const float*)d_in[2];
    const float* embed_b   = (const float*)d_in[3];
    const float* in_proj_w = (const float*)d_in[4];
    const float* in_proj_b = (const float*)d_in[5];
    const float* out_w     = (const float*)d_in[6];
    const float* out_b     = (const float*)d_in[7];
    const float* lin1_w    = (const float*)d_in[8];
    const float* lin1_b    = (const float*)d_in[9];
    const float* lin2_w    = (const float*)d_in[10];
    const float* lin2_b    = (const float*)d_in[11];
    const float* ln1_w     = (const float*)d_in[12];
    const float* ln1_b     = (const float*)d_in[13];
    const float* ln2_w     = (const float*)d_in[14];
    const float* ln2_b     = (const float*)d_in[15];
    const float* attn_w    = (const float*)d_in[16];
    const float* attn_b    = (const float*)d_in[17];
    const float* amp_w     = (const float*)d_in[18];
    const float* amp_b     = (const float*)d_in[19];
    const float* pos_w     = (const float*)d_in[20];
    const float* pos_b     = (const float*)d_in[21];
    const float* atom_w    = (const float*)d_in[22];
    const float* atom_b    = (const float*)d_in[23];
    const float* dmat      = (const float*)d_in[24];
    float* out = (float*)d_out;

    float *p_h, *p_qkv, *p_attno, *p_qkvT, *p_woT, *p_w1T, *p_w2T;
    cudaGetSymbolAddress((void**)&p_h, g_h);
    cudaGetSymbolAddress((void**)&p_qkv, g_qkv);
    cudaGetSymbolAddress((void**)&p_attno, g_attno);
    cudaGetSymbolAddress((void**)&p_qkvT, g_qkvT);
    cudaGetSymbolAddress((void**)&p_woT, g_woT);
    cudaGetSymbolAddress((void**)&p_w1T, g_w1T);
    cudaGetSymbolAddress((void**)&p_w2T, g_w2T);

    cudaFuncSetAttribute(conv_fft_kernel,
                         cudaFuncAttributePreferredSharedMemoryCarveout, 100);

    twid_kernel<<<2, 256>>>();
    ewt_kernel<<<(161 * 128 + 255) / 256, 256>>>(embed_w);
    tq_kernel<<<(6 * 384 * 128 + 255) / 256, 256>>>(in_proj_w);
    ts_kernel<<<(6 * 128 * 128 + 255) / 256, 256>>>(out_w, p_woT);
    ts_kernel<<<(6 * 128 * 128 + 255) / 256, 256>>>(lin1_w, p_w1T);
    ts_kernel<<<(6 * 128 * 128 + 255) / 256, 256>>>(lin2_w, p_w2T);
    filt_kernel<<<64, 256>>>(fb);
    conv_fft_kernel<<<dim3(64, NB), 256>>>(x);

    embed_kernel<<<NB * NF / 8, 128>>>(embed_b);

    qkv_kernel<<<512, 128>>>(p_h, p_qkvT, in_proj_b, p_qkv);
    for (int i = 0; i < 6; i++) {
        attn_kernel<<<dim3(4, NB), 256>>>();
        const float* WnT = (i < 5) ? p_qkvT + (size_t)(i + 1) * 49152 : nullptr;
        const float* bn  = (i < 5) ? in_proj_b + (i + 1) * 384 : nullptr;
        post_kernel<<<512, 128>>>(p_attno,
                                  p_woT + (size_t)i * 16384, out_b + i * 128,
                                  ln1_w + i * 128, ln1_b + i * 128,
                                  p_w1T + (size_t)i * 16384, lin1_b + i * 128,
                                  p_w2T + (size_t)i * 16384, lin2_b + i * 128,
                                  ln2_w + i * 128, ln2_b + i * 128, p_h,
                                  WnT, bn, p_qkv);
    }

    topk_kernel<<<NB, 128>>>(attn_w, attn_b);
    cudaMemsetAsync(d_out, 0, (size_t)out_size * sizeof(float), 0);
    scatter_kernel<<<dim3(16, NB), 128>>>(amp_w, amp_b, pos_w, pos_b,
                                          atom_w, atom_b, dmat, out);
}